// round 1
// baseline (speedup 1.0000x reference)
#include <cuda_runtime.h>
#include <cstdint>

// Problem constants
#define Bb   2048
#define Nn   128
#define Cc   128
#define Hh   4
#define HD   32
#define NW   64
#define M_TOT (Bb * Nn)            // 262144 rows
#define SCALE 0.1767766952966369f  // 1/sqrt(32)

// ---------------------------------------------------------------------------
// Scratch (device globals: allocation-free per harness rules)
// ---------------------------------------------------------------------------
__device__ float g_qkv[(size_t)M_TOT * 3 * Cc];   // [B,N,384]  (402 MB)
__device__ float g_att[(size_t)M_TOT * Cc];       // [B,N,128]  (134 MB)
__device__ float g_qkv_wt[Cc * 3 * Cc];           // [128][384] k-major
__device__ float g_proj_wt[Cc * Cc];              // [128][128] k-major

// ---------------------------------------------------------------------------
// Weight transpose: W[n][k] -> Wt[k][n]  (tiny, one launch)
// ---------------------------------------------------------------------------
__global__ void prep_weights(const float* __restrict__ qkv_w,
                             const float* __restrict__ proj_w) {
    int idx = blockIdx.x * blockDim.x + threadIdx.x;
    if (idx < 3 * Cc * Cc) {
        int n = idx / Cc, k = idx % Cc;
        g_qkv_wt[k * (3 * Cc) + n] = qkv_w[idx];
    }
    if (idx < Cc * Cc) {
        int n = idx / Cc, k = idx % Cc;
        g_proj_wt[k * Cc + n] = proj_w[idx];
    }
}

// ---------------------------------------------------------------------------
// GEMM: out[M][Ntot] = A[M][128] @ Wt[128][Ntot] + bias[Ntot]
// Tiles: BM=64, BN=64, full K=128 in smem. 128 threads, 4x8 per thread.
// smem: as[64][132] (padded, 2-way-conflict scalar a-reads),
//       bs[128][64]  (k-major, conflict-free vector b-reads)
// ---------------------------------------------------------------------------
#define GEMM_SMEM ((64 * 132 + 128 * 64) * 4)

__global__ __launch_bounds__(128)
void gemm_bias(const float* __restrict__ A, const float* __restrict__ Wt,
               const float* __restrict__ bias, float* __restrict__ out,
               int Ntot) {
    extern __shared__ float sm[];
    float* as = sm;               // [64][132]
    float* bs = sm + 64 * 132;    // [128][64]

    const int mBase = blockIdx.x * 64;
    const int nBase = blockIdx.y * 64;
    const int tid   = threadIdx.x;

    // Load A tile (coalesced float4 reads, contiguous float4 smem stores)
    const float4* Ag = reinterpret_cast<const float4*>(A + (size_t)mBase * 128);
#pragma unroll
    for (int it = 0; it < 16; ++it) {
        int idx = it * 128 + tid;        // 0..2047 float4s
        int m = idx >> 5, k4 = idx & 31;
        float4 v = Ag[(size_t)m * 32 + k4];
        *reinterpret_cast<float4*>(&as[m * 132 + k4 * 4]) = v;
    }
    // Load B tile: Wt[k][nBase..nBase+64)
#pragma unroll
    for (int it = 0; it < 16; ++it) {
        int idx = it * 128 + tid;        // 0..2047 float4s
        int k = idx >> 4, n4 = idx & 15;
        float4 v = *reinterpret_cast<const float4*>(
            &Wt[(size_t)k * Ntot + nBase + n4 * 4]);
        *reinterpret_cast<float4*>(&bs[k * 64 + n4 * 4]) = v;
    }
    __syncthreads();

    const int tr = tid >> 3;   // 0..15  (4 rows each)
    const int tc = tid & 7;    // 0..7   (8 cols each)

    float acc[4][8];
#pragma unroll
    for (int i = 0; i < 4; ++i)
#pragma unroll
        for (int j = 0; j < 8; ++j) acc[i][j] = 0.f;

    const float* asp = &as[(tr * 4) * 132];
    const float* bsp = &bs[tc * 8];

#pragma unroll 4
    for (int k = 0; k < 128; ++k) {
        float a0 = asp[k];
        float a1 = asp[132 + k];
        float a2 = asp[264 + k];
        float a3 = asp[396 + k];
        float4 b0 = *reinterpret_cast<const float4*>(&bsp[k * 64]);
        float4 b1 = *reinterpret_cast<const float4*>(&bsp[k * 64 + 4]);
        float bb[8] = {b0.x, b0.y, b0.z, b0.w, b1.x, b1.y, b1.z, b1.w};
#pragma unroll
        for (int j = 0; j < 8; ++j) {
            acc[0][j] += a0 * bb[j];
            acc[1][j] += a1 * bb[j];
            acc[2][j] += a2 * bb[j];
            acc[3][j] += a3 * bb[j];
        }
    }

    // Epilogue: + bias, float4 stores
    float br[8];
#pragma unroll
    for (int j = 0; j < 8; ++j) br[j] = bias[nBase + tc * 8 + j];

#pragma unroll
    for (int i = 0; i < 4; ++i) {
        size_t row = (size_t)(mBase + tr * 4 + i);
        float4 o0 = {acc[i][0] + br[0], acc[i][1] + br[1],
                     acc[i][2] + br[2], acc[i][3] + br[3]};
        float4 o1 = {acc[i][4] + br[4], acc[i][5] + br[5],
                     acc[i][6] + br[6], acc[i][7] + br[7]};
        float* op = out + row * Ntot + nBase + tc * 8;
        *reinterpret_cast<float4*>(op)     = o0;
        *reinterpret_cast<float4*>(op + 4) = o1;
    }
}

// ---------------------------------------------------------------------------
// Attention: one block per (b,h). 128 threads, thread i owns query row i.
// smem: ks[128][32], vs[128][32], sc[128][129] (pad -> bank (i+j)%32, no
// conflicts in row-wise access). Mask preloaded coalesced into sc; softmax
// normalization folded into PV epilogue.
// ---------------------------------------------------------------------------
#define ATTN_SMEM ((128 * 32 * 2 + 128 * 129) * 4)

__global__ __launch_bounds__(128)
void attn_kernel(const float* __restrict__ qkv, const float* __restrict__ mask,
                 float* __restrict__ att) {
    extern __shared__ float sm[];
    float* ks = sm;            // [128][32]
    float* vs = sm + 4096;     // [128][32]
    float* sc = sm + 8192;     // [128][129]

    const int bh  = blockIdx.x;
    const int b   = bh >> 2;
    const int h   = bh & 3;
    const int w   = b & (NW - 1);
    const int tid = threadIdx.x;   // = query row i

    const float* base = qkv + (size_t)b * Nn * 384;

    // Load K,V rows (row tid): 128B contiguous per thread
    {
        const float4* kr = reinterpret_cast<const float4*>(base + (size_t)tid * 384 + 128 + h * 32);
        const float4* vr = reinterpret_cast<const float4*>(base + (size_t)tid * 384 + 256 + h * 32);
        float4* kd = reinterpret_cast<float4*>(&ks[tid * 32]);
        float4* vd = reinterpret_cast<float4*>(&vs[tid * 32]);
#pragma unroll
        for (int j = 0; j < 8; ++j) { kd[j] = kr[j]; vd[j] = vr[j]; }
    }

    // Preload mask window into sc (coalesced global reads, scalar smem stores)
    const float* mrow = mask + (size_t)w * Nn * Nn;
#pragma unroll
    for (int it = 0; it < 32; ++it) {
        int idx = it * 128 + tid;          // float4 index, 0..4095
        int i = idx >> 5, j4 = idx & 31;
        float4 v = *reinterpret_cast<const float4*>(&mrow[i * 128 + j4 * 4]);
        float* d = &sc[i * 129 + j4 * 4];
        d[0] = v.x; d[1] = v.y; d[2] = v.z; d[3] = v.w;
    }

    // Load q row into registers
    float q[32];
    {
        const float4* qr = reinterpret_cast<const float4*>(base + (size_t)tid * 384 + h * 32);
#pragma unroll
        for (int j = 0; j < 8; ++j) *reinterpret_cast<float4*>(&q[j * 4]) = qr[j];
    }

    __syncthreads();

    float* myrow = &sc[tid * 129];

    // S = q.K^T * scale + mask   (4 partial sums for ILP)
#pragma unroll 2
    for (int j = 0; j < 128; ++j) {
        const float* kr = &ks[j * 32];
        float s0 = 0.f, s1 = 0.f, s2 = 0.f, s3 = 0.f;
#pragma unroll
        for (int d = 0; d < 32; d += 4) {
            s0 += q[d + 0] * kr[d + 0];
            s1 += q[d + 1] * kr[d + 1];
            s2 += q[d + 2] * kr[d + 2];
            s3 += q[d + 3] * kr[d + 3];
        }
        myrow[j] = ((s0 + s1) + (s2 + s3)) * SCALE + myrow[j];
    }

    // Softmax (unnormalized exp; fold 1/sum into epilogue)
    float mx = -1e30f;
#pragma unroll 4
    for (int j = 0; j < 128; ++j) mx = fmaxf(mx, myrow[j]);
    float sum = 0.f;
#pragma unroll 4
    for (int j = 0; j < 128; ++j) {
        float e = __expf(myrow[j] - mx);
        myrow[j] = e;
        sum += e;
    }
    const float inv = 1.f / sum;

    // O = P.V  (32 independent accumulator chains)
    float acc[32];
#pragma unroll
    for (int d = 0; d < 32; ++d) acc[d] = 0.f;
#pragma unroll 2
    for (int j = 0; j < 128; ++j) {
        float p = myrow[j];
        const float* vr = &vs[j * 32];
#pragma unroll
        for (int d = 0; d < 32; ++d) acc[d] += p * vr[d];
    }

    float* op = att + ((size_t)b * Nn + tid) * Cc + h * 32;
#pragma unroll
    for (int d4 = 0; d4 < 8; ++d4) {
        float4 o = {acc[d4 * 4 + 0] * inv, acc[d4 * 4 + 1] * inv,
                    acc[d4 * 4 + 2] * inv, acc[d4 * 4 + 3] * inv};
        *reinterpret_cast<float4*>(&op[d4 * 4]) = o;
    }
}

// ---------------------------------------------------------------------------
// Launch
// ---------------------------------------------------------------------------
extern "C" void kernel_launch(void* const* d_in, const int* in_sizes, int n_in,
                              void* d_out, int out_size) {
    const float* x      = (const float*)d_in[0];
    const float* mask   = (const float*)d_in[1];
    const float* qkv_w  = (const float*)d_in[2];
    const float* qkv_b  = (const float*)d_in[3];
    const float* proj_w = (const float*)d_in[4];
    const float* proj_b = (const float*)d_in[5];
    float* out = (float*)d_out;

    float *p_qkv, *p_att, *p_qwt, *p_pwt;
    cudaGetSymbolAddress((void**)&p_qkv, g_qkv);
    cudaGetSymbolAddress((void**)&p_att, g_att);
    cudaGetSymbolAddress((void**)&p_qwt, g_qkv_wt);
    cudaGetSymbolAddress((void**)&p_pwt, g_proj_wt);

    cudaFuncSetAttribute(gemm_bias, cudaFuncAttributeMaxDynamicSharedMemorySize, GEMM_SMEM);
    cudaFuncSetAttribute(attn_kernel, cudaFuncAttributeMaxDynamicSharedMemorySize, ATTN_SMEM);

    // 1) transpose weights to k-major
    prep_weights<<<192, 256>>>(qkv_w, proj_w);

    // 2) QKV projection: [262144,128] @ [128,384] + b
    gemm_bias<<<dim3(M_TOT / 64, 6), 128, GEMM_SMEM>>>(x, p_qwt, qkv_b, p_qkv, 384);

    // 3) windowed attention per (b,h)
    attn_kernel<<<Bb * Hh, 128, ATTN_SMEM>>>(p_qkv, mask, p_att);

    // 4) output projection: [262144,128] @ [128,128] + b
    gemm_bias<<<dim3(M_TOT / 64, 2), 128, GEMM_SMEM>>>(p_att, p_pwt, proj_b, out, 128);
}

// round 3
// speedup vs baseline: 1.7337x; 1.7337x over previous
#include <cuda_runtime.h>
#include <cstdint>

// Problem constants
#define Bb   2048
#define Nn   128
#define Cc   128
#define Hh   4
#define NW   64
#define M_TOT (Bb * Nn)            // 262144 rows
#define SCALE 0.1767766952966369f  // 1/sqrt(32)

// ---------------------------------------------------------------------------
// Helpers (baseline ISA only: ldmatrix + mma.sync, no tcgen05)
// ---------------------------------------------------------------------------
__device__ __forceinline__ uint32_t smem_u32(const void* p) {
    uint32_t a;
    asm("{ .reg .u64 t; cvta.to.shared.u64 t, %1; cvt.u32.u64 %0, t; }"
        : "=r"(a) : "l"(p));
    return a;
}
__device__ __forceinline__ uint32_t f2tf32(float f) {
    uint32_t u;
    asm("cvt.rna.tf32.f32 %0, %1;" : "=r"(u) : "f"(f));
    return u;
}
__device__ __forceinline__ void ldsm4(uint32_t& r0, uint32_t& r1, uint32_t& r2,
                                      uint32_t& r3, uint32_t addr) {
    asm volatile("ldmatrix.sync.aligned.m8n8.x4.shared.b16 {%0,%1,%2,%3}, [%4];"
                 : "=r"(r0), "=r"(r1), "=r"(r2), "=r"(r3) : "r"(addr));
}
__device__ __forceinline__ void mma_tf32(float* c, const uint32_t* a,
                                         const uint32_t* b) {
    asm volatile(
        "mma.sync.aligned.m16n8k8.row.col.f32.tf32.tf32.f32 "
        "{%0,%1,%2,%3}, {%4,%5,%6,%7}, {%8,%9}, {%0,%1,%2,%3};"
        : "+f"(c[0]), "+f"(c[1]), "+f"(c[2]), "+f"(c[3])
        : "r"(a[0]), "r"(a[1]), "r"(a[2]), "r"(a[3]), "r"(b[0]), "r"(b[1]));
}
__device__ __forceinline__ uint32_t sw128(uint32_t off) {
    return off ^ ((off >> 3) & 0x70);
}

// ---------------------------------------------------------------------------
// Scratch
// ---------------------------------------------------------------------------
__device__ float g_qkv[(size_t)M_TOT * 3 * Cc];   // [B,N,384]
__device__ float g_att[(size_t)M_TOT * Cc];       // [B,N,128]

// ---------------------------------------------------------------------------
// tf32 mma.sync GEMM: out[M][Ntot] = A[M][128] @ W[Ntot][128]^T + bias
// Tile 128x64x128, 256 threads (8 warps: 4m x 2n), warp tile 32x32.
// smem: A 4 chunks x [128 rows][32 f32, SW128], B 4 chunks x [64][32].
// 96KB/CTA -> 2 CTAs/SM (cross-CTA load/compute overlap).
// ---------------------------------------------------------------------------
#define GSM_A     0
#define GSM_B     65536
#define GSM_TOTAL 98304

__global__ __launch_bounds__(256, 2)
void gemm_mma(const float* __restrict__ A, const float* __restrict__ W,
              const float* __restrict__ bias, float* __restrict__ out, int Ntot) {
    extern __shared__ char smem[];
    const uint32_t sA = smem_u32(smem) + GSM_A;
    const uint32_t sB = smem_u32(smem) + GSM_B;
    const int tid  = threadIdx.x;
    const int wid  = tid >> 5;
    const int lane = tid & 31;
    const int nBase = blockIdx.x * 64;
    const int mBase = blockIdx.y * 128;
    const int wm = wid & 3;   // 0..3 : 32 rows each
    const int wn = wid >> 2;  // 0..1 : 32 cols each

    // ---- Global -> smem (coalesced LDG.128, cvt.rna to tf32, swizzled STS) ----
    const float4* A4 = reinterpret_cast<const float4*>(A + (size_t)mBase * 128);
    const float4* B4 = reinterpret_cast<const float4*>(W + (size_t)nBase * 128);
#pragma unroll
    for (int it = 0; it < 16; ++it) {           // A: 4096 float4
        int idx = it * 256 + tid;
        int m = idx >> 5, q = idx & 31;
        int c = q >> 3, k4 = q & 7;
        float4 v = A4[(size_t)m * 32 + q];
        uint4 u = {f2tf32(v.x), f2tf32(v.y), f2tf32(v.z), f2tf32(v.w)};
        *reinterpret_cast<uint4*>(
            (char*)smem + GSM_A + c * 16384 + sw128(m * 128 + k4 * 16)) = u;
    }
#pragma unroll
    for (int it = 0; it < 8; ++it) {            // B: 2048 float4
        int idx = it * 256 + tid;
        int n = idx >> 5, q = idx & 31;
        int c = q >> 3, k4 = q & 7;
        float4 v = B4[(size_t)n * 32 + q];
        uint4 u = {f2tf32(v.x), f2tf32(v.y), f2tf32(v.z), f2tf32(v.w)};
        *reinterpret_cast<uint4*>(
            (char*)smem + GSM_B + c * 8192 + sw128(n * 128 + k4 * 16)) = u;
    }
    __syncthreads();

    // ---- Per-lane ldmatrix source addresses ----
    // A tiles: t=lane>>3: row += (t&1)*8, unit += t>>1.  a0..a3 layout match.
    // B tiles: t=lane>>3: row += (t>>1)*8, unit += t&1.  -> {b0,b1} x 2 nfrags.
    const int r8 = lane & 7, t = lane >> 3;
    const int a_row0 = wm * 32 + (t & 1) * 8 + r8;           // + mf*16
    const int a_us   = t >> 1;
    const int b_row0 = wn * 32 + (t >> 1) * 8 + r8;          // + p*16
    const int b_us   = t & 1;

    float acc[2][4][4];
#pragma unroll
    for (int i = 0; i < 2; ++i)
#pragma unroll
        for (int j = 0; j < 4; ++j)
#pragma unroll
            for (int k = 0; k < 4; ++k) acc[i][j][k] = 0.f;

    // ---- Mainloop: 16 k-steps of k=8 ----
#pragma unroll
    for (int s = 0; s < 16; ++s) {
        const int c = s >> 2;
        const int ku = (s & 3) * 2;
        uint32_t af[2][4], bf[4][2];
#pragma unroll
        for (int mf = 0; mf < 2; ++mf) {
            int row = a_row0 + mf * 16;
            uint32_t addr = sA + c * 16384 + row * 128 +
                            (((ku + a_us) * 16) ^ ((row & 7) * 16));
            ldsm4(af[mf][0], af[mf][1], af[mf][2], af[mf][3], addr);
        }
#pragma unroll
        for (int p = 0; p < 2; ++p) {
            int row = b_row0 + p * 16;
            uint32_t addr = sB + c * 8192 + row * 128 +
                            (((ku + b_us) * 16) ^ ((row & 7) * 16));
            ldsm4(bf[p * 2][0], bf[p * 2][1], bf[p * 2 + 1][0], bf[p * 2 + 1][1],
                  addr);
        }
#pragma unroll
        for (int mf = 0; mf < 2; ++mf)
#pragma unroll
            for (int nf = 0; nf < 4; ++nf)
                mma_tf32(acc[mf][nf], af[mf], bf[nf]);
    }

    // ---- Epilogue: + bias, float2 stores (quad-coalesced 32B sectors) ----
#pragma unroll
    for (int mf = 0; mf < 2; ++mf) {
        const int rowg = mBase + wm * 32 + mf * 16 + (lane >> 2);
#pragma unroll
        for (int nf = 0; nf < 4; ++nf) {
            const int col = nBase + wn * 32 + nf * 8 + (lane & 3) * 2;
            float2 bv = *reinterpret_cast<const float2*>(&bias[col]);
            float2 o0 = {acc[mf][nf][0] + bv.x, acc[mf][nf][1] + bv.y};
            float2 o1 = {acc[mf][nf][2] + bv.x, acc[mf][nf][3] + bv.y};
            *reinterpret_cast<float2*>(out + (size_t)rowg * Ntot + col) = o0;
            *reinterpret_cast<float2*>(out + (size_t)(rowg + 8) * Ntot + col) = o1;
        }
    }
}

// ---------------------------------------------------------------------------
// Attention: one block per (b,h). 128 threads, thread i owns query row i.
// ---------------------------------------------------------------------------
#define ATTN_SMEM ((128 * 32 * 2 + 128 * 129) * 4)

__global__ __launch_bounds__(128)
void attn_kernel(const float* __restrict__ qkv, const float* __restrict__ mask,
                 float* __restrict__ att) {
    extern __shared__ float sm[];
    float* ks = sm;            // [128][32]
    float* vs = sm + 4096;     // [128][32]
    float* sc = sm + 8192;     // [128][129]

    const int bh  = blockIdx.x;
    const int b   = bh >> 2;
    const int h   = bh & 3;
    const int w   = b & (NW - 1);
    const int tid = threadIdx.x;   // query row i

    const float* base = qkv + (size_t)b * Nn * 384;

    {
        const float4* kr = reinterpret_cast<const float4*>(base + (size_t)tid * 384 + 128 + h * 32);
        const float4* vr = reinterpret_cast<const float4*>(base + (size_t)tid * 384 + 256 + h * 32);
        float4* kd = reinterpret_cast<float4*>(&ks[tid * 32]);
        float4* vd = reinterpret_cast<float4*>(&vs[tid * 32]);
#pragma unroll
        for (int j = 0; j < 8; ++j) { kd[j] = kr[j]; vd[j] = vr[j]; }
    }

    const float* mrow = mask + (size_t)w * Nn * Nn;
#pragma unroll
    for (int it = 0; it < 32; ++it) {
        int idx = it * 128 + tid;
        int i = idx >> 5, j4 = idx & 31;
        float4 v = *reinterpret_cast<const float4*>(&mrow[i * 128 + j4 * 4]);
        float* d = &sc[i * 129 + j4 * 4];
        d[0] = v.x; d[1] = v.y; d[2] = v.z; d[3] = v.w;
    }

    float q[32];
    {
        const float4* qr = reinterpret_cast<const float4*>(base + (size_t)tid * 384 + h * 32);
#pragma unroll
        for (int j = 0; j < 8; ++j) *reinterpret_cast<float4*>(&q[j * 4]) = qr[j];
    }

    __syncthreads();

    float* myrow = &sc[tid * 129];

#pragma unroll 2
    for (int j = 0; j < 128; ++j) {
        const float4* kr = reinterpret_cast<const float4*>(&ks[j * 32]);
        float s0 = 0.f, s1 = 0.f, s2 = 0.f, s3 = 0.f;
#pragma unroll
        for (int t = 0; t < 8; ++t) {
            float4 kv = kr[t];
            s0 += q[t * 4 + 0] * kv.x;
            s1 += q[t * 4 + 1] * kv.y;
            s2 += q[t * 4 + 2] * kv.z;
            s3 += q[t * 4 + 3] * kv.w;
        }
        myrow[j] = ((s0 + s1) + (s2 + s3)) * SCALE + myrow[j];
    }

    float mx = -1e30f;
#pragma unroll 4
    for (int j = 0; j < 128; ++j) mx = fmaxf(mx, myrow[j]);
    float sum = 0.f;
#pragma unroll 4
    for (int j = 0; j < 128; ++j) {
        float e = __expf(myrow[j] - mx);
        myrow[j] = e;
        sum += e;
    }
    const float inv = 1.f / sum;

    float acc[32];
#pragma unroll
    for (int d = 0; d < 32; ++d) acc[d] = 0.f;
#pragma unroll 2
    for (int j = 0; j < 128; ++j) {
        float p = myrow[j];
        const float4* vr = reinterpret_cast<const float4*>(&vs[j * 32]);
#pragma unroll
        for (int t = 0; t < 8; ++t) {
            float4 vv = vr[t];
            acc[t * 4 + 0] += p * vv.x;
            acc[t * 4 + 1] += p * vv.y;
            acc[t * 4 + 2] += p * vv.z;
            acc[t * 4 + 3] += p * vv.w;
        }
    }

    float* op = att + ((size_t)b * Nn + tid) * Cc + h * 32;
#pragma unroll
    for (int d4 = 0; d4 < 8; ++d4) {
        float4 o = {acc[d4 * 4 + 0] * inv, acc[d4 * 4 + 1] * inv,
                    acc[d4 * 4 + 2] * inv, acc[d4 * 4 + 3] * inv};
        *reinterpret_cast<float4*>(&op[d4 * 4]) = o;
    }
}

// ---------------------------------------------------------------------------
// Launch
// ---------------------------------------------------------------------------
extern "C" void kernel_launch(void* const* d_in, const int* in_sizes, int n_in,
                              void* d_out, int out_size) {
    const float* x      = (const float*)d_in[0];
    const float* mask   = (const float*)d_in[1];
    const float* qkv_w  = (const float*)d_in[2];
    const float* qkv_b  = (const float*)d_in[3];
    const float* proj_w = (const float*)d_in[4];
    const float* proj_b = (const float*)d_in[5];
    float* out = (float*)d_out;

    float *p_qkv, *p_att;
    cudaGetSymbolAddress((void**)&p_qkv, g_qkv);
    cudaGetSymbolAddress((void**)&p_att, g_att);

    cudaFuncSetAttribute(gemm_mma, cudaFuncAttributeMaxDynamicSharedMemorySize, GSM_TOTAL);
    cudaFuncSetAttribute(attn_kernel, cudaFuncAttributeMaxDynamicSharedMemorySize, ATTN_SMEM);

    // 1) QKV projection: [262144,128] @ [384,128]^T + b   (mma.sync tf32)
    gemm_mma<<<dim3(6, M_TOT / 128), 256, GSM_TOTAL>>>(x, qkv_w, qkv_b, p_qkv, 384);

    // 2) windowed attention per (b,h)
    attn_kernel<<<Bb * Hh, 128, ATTN_SMEM>>>(p_qkv, mask, p_att);

    // 3) output projection: [262144,128] @ [128,128]^T + b   (mma.sync tf32)
    gemm_mma<<<dim3(2, M_TOT / 128), 256, GSM_TOTAL>>>(p_att, proj_w, proj_b, out, 128);
}

// round 4
// speedup vs baseline: 2.9993x; 1.7300x over previous
#include <cuda_runtime.h>
#include <cstdint>

// Problem constants
#define Bb   2048
#define Nn   128
#define Cc   128
#define Hh   4
#define NW   64
#define M_TOT (Bb * Nn)            // 262144 rows
#define SCALE 0.1767766952966369f  // 1/sqrt(32)

// ---------------------------------------------------------------------------
// Helpers (baseline ISA: ldmatrix + mma.sync)
// ---------------------------------------------------------------------------
__device__ __forceinline__ uint32_t smem_u32(const void* p) {
    uint32_t a;
    asm("{ .reg .u64 t; cvta.to.shared.u64 t, %1; cvt.u32.u64 %0, t; }"
        : "=r"(a) : "l"(p));
    return a;
}
__device__ __forceinline__ uint32_t f2tf32(float f) {
    uint32_t u;
    asm("cvt.rna.tf32.f32 %0, %1;" : "=r"(u) : "f"(f));
    return u;
}
__device__ __forceinline__ void ldsm4(uint32_t& r0, uint32_t& r1, uint32_t& r2,
                                      uint32_t& r3, uint32_t addr) {
    asm volatile("ldmatrix.sync.aligned.m8n8.x4.shared.b16 {%0,%1,%2,%3}, [%4];"
                 : "=r"(r0), "=r"(r1), "=r"(r2), "=r"(r3) : "r"(addr));
}
__device__ __forceinline__ void mma_tf32(float* c, const uint32_t* a,
                                         const uint32_t* b) {
    asm volatile(
        "mma.sync.aligned.m16n8k8.row.col.f32.tf32.tf32.f32 "
        "{%0,%1,%2,%3}, {%4,%5,%6,%7}, {%8,%9}, {%0,%1,%2,%3};"
        : "+f"(c[0]), "+f"(c[1]), "+f"(c[2]), "+f"(c[3])
        : "r"(a[0]), "r"(a[1]), "r"(a[2]), "r"(a[3]), "r"(b[0]), "r"(b[1]));
}
__device__ __forceinline__ uint32_t sw128(uint32_t off) {
    return off ^ ((off >> 3) & 0x70);
}

// ---------------------------------------------------------------------------
// Scratch
// ---------------------------------------------------------------------------
__device__ float g_qkv[(size_t)M_TOT * 3 * Cc];   // [B,N,384]
__device__ float g_att[(size_t)M_TOT * Cc];       // [B,N,128]

// ---------------------------------------------------------------------------
// tf32 mma.sync GEMM (unchanged from round 3)
// ---------------------------------------------------------------------------
#define GSM_A     0
#define GSM_B     65536
#define GSM_TOTAL 98304

__global__ __launch_bounds__(256, 2)
void gemm_mma(const float* __restrict__ A, const float* __restrict__ W,
              const float* __restrict__ bias, float* __restrict__ out, int Ntot) {
    extern __shared__ char smem[];
    const uint32_t sA = smem_u32(smem) + GSM_A;
    const uint32_t sB = smem_u32(smem) + GSM_B;
    const int tid  = threadIdx.x;
    const int wid  = tid >> 5;
    const int lane = tid & 31;
    const int nBase = blockIdx.x * 64;
    const int mBase = blockIdx.y * 128;
    const int wm = wid & 3;
    const int wn = wid >> 2;

    const float4* A4 = reinterpret_cast<const float4*>(A + (size_t)mBase * 128);
    const float4* B4 = reinterpret_cast<const float4*>(W + (size_t)nBase * 128);
#pragma unroll
    for (int it = 0; it < 16; ++it) {
        int idx = it * 256 + tid;
        int m = idx >> 5, q = idx & 31;
        int c = q >> 3, k4 = q & 7;
        float4 v = A4[(size_t)m * 32 + q];
        uint4 u = {f2tf32(v.x), f2tf32(v.y), f2tf32(v.z), f2tf32(v.w)};
        *reinterpret_cast<uint4*>(
            (char*)smem + GSM_A + c * 16384 + sw128(m * 128 + k4 * 16)) = u;
    }
#pragma unroll
    for (int it = 0; it < 8; ++it) {
        int idx = it * 256 + tid;
        int n = idx >> 5, q = idx & 31;
        int c = q >> 3, k4 = q & 7;
        float4 v = B4[(size_t)n * 32 + q];
        uint4 u = {f2tf32(v.x), f2tf32(v.y), f2tf32(v.z), f2tf32(v.w)};
        *reinterpret_cast<uint4*>(
            (char*)smem + GSM_B + c * 8192 + sw128(n * 128 + k4 * 16)) = u;
    }
    __syncthreads();

    const int r8 = lane & 7, t = lane >> 3;
    const int a_row0 = wm * 32 + (t & 1) * 8 + r8;
    const int a_us   = t >> 1;
    const int b_row0 = wn * 32 + (t >> 1) * 8 + r8;
    const int b_us   = t & 1;

    float acc[2][4][4];
#pragma unroll
    for (int i = 0; i < 2; ++i)
#pragma unroll
        for (int j = 0; j < 4; ++j)
#pragma unroll
            for (int k = 0; k < 4; ++k) acc[i][j][k] = 0.f;

#pragma unroll
    for (int s = 0; s < 16; ++s) {
        const int c = s >> 2;
        const int ku = (s & 3) * 2;
        uint32_t af[2][4], bf[4][2];
#pragma unroll
        for (int mf = 0; mf < 2; ++mf) {
            int row = a_row0 + mf * 16;
            uint32_t addr = sA + c * 16384 + row * 128 +
                            (((ku + a_us) * 16) ^ ((row & 7) * 16));
            ldsm4(af[mf][0], af[mf][1], af[mf][2], af[mf][3], addr);
        }
#pragma unroll
        for (int p = 0; p < 2; ++p) {
            int row = b_row0 + p * 16;
            uint32_t addr = sB + c * 8192 + row * 128 +
                            (((ku + b_us) * 16) ^ ((row & 7) * 16));
            ldsm4(bf[p * 2][0], bf[p * 2][1], bf[p * 2 + 1][0], bf[p * 2 + 1][1],
                  addr);
        }
#pragma unroll
        for (int mf = 0; mf < 2; ++mf)
#pragma unroll
            for (int nf = 0; nf < 4; ++nf)
                mma_tf32(acc[mf][nf], af[mf], bf[nf]);
    }

#pragma unroll
    for (int mf = 0; mf < 2; ++mf) {
        const int rowg = mBase + wm * 32 + mf * 16 + (lane >> 2);
#pragma unroll
        for (int nf = 0; nf < 4; ++nf) {
            const int col = nBase + wn * 32 + nf * 8 + (lane & 3) * 2;
            float2 bv = *reinterpret_cast<const float2*>(&bias[col]);
            float2 o0 = {acc[mf][nf][0] + bv.x, acc[mf][nf][1] + bv.y};
            float2 o1 = {acc[mf][nf][2] + bv.x, acc[mf][nf][3] + bv.y};
            *reinterpret_cast<float2*>(out + (size_t)rowg * Ntot + col) = o0;
            *reinterpret_cast<float2*>(out + (size_t)(rowg + 8) * Ntot + col) = o1;
        }
    }
}

// ---------------------------------------------------------------------------
// Tensor-core attention: one block per (b,h), 4 warps, warp w owns 32 q-rows.
// S = (Q*SCALE)@K^T + mask via mma tf32 (K split hi/lo for accuracy),
// register softmax, P -> smem (overlaying Q/K regions), PV via mma tf32.
// smem: [Q 16K][Khi 16K][Klo 16K][Vt 16K][P-chunk3 16K] = 80KB -> 2 CTAs/SM.
// P chunks 0..2 overlay Q/Khi/Klo (dead after S; one __syncthreads hazard).
// ---------------------------------------------------------------------------
#define ASM_Q    0
#define ASM_KHI  16384
#define ASM_KLO  32768
#define ASM_VT   49152
#define ASM_P3   65536
#define ATTN_SMEM_TOT 81920

__device__ __forceinline__ uint32_t pchunk_off(int c) {
    return (c == 3) ? (uint32_t)ASM_P3 : (uint32_t)(c * 16384);
}

__global__ __launch_bounds__(128)
void attn_mma(const float* __restrict__ qkv, const float* __restrict__ mask,
              float* __restrict__ att) {
    extern __shared__ char smem[];
    const uint32_t sb = smem_u32(smem);
    const int tid = threadIdx.x, lane = tid & 31, w = tid >> 5;
    const int bh = blockIdx.x, b = bh >> 2, h = bh & 3, win = b & (NW - 1);
    const float* base  = qkv + (size_t)b * Nn * 384;
    const float* mbase = mask + (size_t)win * Nn * Nn;

    const int qrow = lane >> 2;        // 0..7
    const int qc   = (lane & 3) * 2;   // 0,2,4,6

    // ---- Accumulators initialized from mask (S = QK^T accumulates on top) ----
    float acc[2][16][4];
#pragma unroll
    for (int mf = 0; mf < 2; ++mf) {
        const float* mr = mbase + (w * 32 + mf * 16 + qrow) * Nn + qc;
#pragma unroll
        for (int nf = 0; nf < 16; ++nf) {
            float2 m0 = *reinterpret_cast<const float2*>(mr + nf * 8);
            float2 m1 = *reinterpret_cast<const float2*>(mr + 8 * Nn + nf * 8);
            acc[mf][nf][0] = m0.x; acc[mf][nf][1] = m0.y;
            acc[mf][nf][2] = m1.x; acc[mf][nf][3] = m1.y;
        }
    }

    // ---- Load Q(scaled), K(hi/lo split), V(transposed) into smem ----
    {
        const float4* qr = reinterpret_cast<const float4*>(base + (size_t)tid * 384 + h * 32);
        const float4* kr = reinterpret_cast<const float4*>(base + (size_t)tid * 384 + 128 + h * 32);
        const float4* vr = reinterpret_cast<const float4*>(base + (size_t)tid * 384 + 256 + h * 32);
        const int vc = tid >> 5, vj = tid & 31;
#pragma unroll
        for (int t = 0; t < 8; ++t) {
            uint32_t so = sw128(tid * 128 + t * 16);

            float4 qv = qr[t];
            uint4 qs = {f2tf32(qv.x * SCALE), f2tf32(qv.y * SCALE),
                        f2tf32(qv.z * SCALE), f2tf32(qv.w * SCALE)};
            *reinterpret_cast<uint4*>(smem + ASM_Q + so) = qs;

            float4 kv = kr[t];
            uint4 kh = {f2tf32(kv.x), f2tf32(kv.y), f2tf32(kv.z), f2tf32(kv.w)};
            uint4 kl = {f2tf32(kv.x - __uint_as_float(kh.x)),
                        f2tf32(kv.y - __uint_as_float(kh.y)),
                        f2tf32(kv.z - __uint_as_float(kh.z)),
                        f2tf32(kv.w - __uint_as_float(kh.w))};
            *reinterpret_cast<uint4*>(smem + ASM_KHI + so) = kh;
            *reinterpret_cast<uint4*>(smem + ASM_KLO + so) = kl;

            float4 vv = vr[t];   // transpose: Vt[d][j=tid], chunked by j
            char* vb = smem + ASM_VT + vc * 4096;
            *reinterpret_cast<uint32_t*>(vb + sw128((t * 4 + 0) * 128 + vj * 4)) = f2tf32(vv.x);
            *reinterpret_cast<uint32_t*>(vb + sw128((t * 4 + 1) * 128 + vj * 4)) = f2tf32(vv.y);
            *reinterpret_cast<uint32_t*>(vb + sw128((t * 4 + 2) * 128 + vj * 4)) = f2tf32(vv.z);
            *reinterpret_cast<uint32_t*>(vb + sw128((t * 4 + 3) * 128 + vj * 4)) = f2tf32(vv.w);
        }
    }
    __syncthreads();

    const int r8 = lane & 7, t4 = lane >> 3;
    const int a_us = t4 >> 1, b_us = t4 & 1;
    const int a_row_base = w * 32 + (t4 & 1) * 8 + r8;
    const int b_row_base = (t4 >> 1) * 8 + r8;

    // ---- S mma: 4 k-steps (hd=32), K as hi+lo ----
#pragma unroll
    for (int s = 0; s < 4; ++s) {
        const int ku = s * 2;
        uint32_t qf[2][4];
#pragma unroll
        for (int mf = 0; mf < 2; ++mf) {
            int row = a_row_base + mf * 16;
            uint32_t addr = sb + ASM_Q + row * 128 +
                            (((ku + a_us) * 16) ^ ((row & 7) * 16));
            ldsm4(qf[mf][0], qf[mf][1], qf[mf][2], qf[mf][3], addr);
        }
#pragma unroll
        for (int p = 0; p < 8; ++p) {
            int row = b_row_base + p * 16;
            uint32_t off = row * 128 + (((ku + b_us) * 16) ^ ((row & 7) * 16));
            uint32_t kh[2][2], kl[2][2];
            ldsm4(kh[0][0], kh[0][1], kh[1][0], kh[1][1], sb + ASM_KHI + off);
            ldsm4(kl[0][0], kl[0][1], kl[1][0], kl[1][1], sb + ASM_KLO + off);
#pragma unroll
            for (int mf = 0; mf < 2; ++mf) {
#pragma unroll
                for (int e = 0; e < 2; ++e) {
                    mma_tf32(acc[mf][p * 2 + e], qf[mf], kh[e]);
                    mma_tf32(acc[mf][p * 2 + e], qf[mf], kl[e]);
                }
            }
        }
    }
    __syncthreads();   // Q/K reads done in ALL warps before P overwrites them

    // ---- Register softmax (rows spread over quads) ----
    float inv[2][2];
#pragma unroll
    for (int mf = 0; mf < 2; ++mf) {
#pragma unroll
        for (int hf = 0; hf < 2; ++hf) {
            float mx = -1e30f;
#pragma unroll
            for (int nf = 0; nf < 16; ++nf)
                mx = fmaxf(mx, fmaxf(acc[mf][nf][hf * 2], acc[mf][nf][hf * 2 + 1]));
            mx = fmaxf(mx, __shfl_xor_sync(0xffffffffu, mx, 1));
            mx = fmaxf(mx, __shfl_xor_sync(0xffffffffu, mx, 2));
            float sum = 0.f;
#pragma unroll
            for (int nf = 0; nf < 16; ++nf) {
                float e0 = __expf(acc[mf][nf][hf * 2] - mx);
                float e1 = __expf(acc[mf][nf][hf * 2 + 1] - mx);
                acc[mf][nf][hf * 2] = e0;
                acc[mf][nf][hf * 2 + 1] = e1;
                sum += e0 + e1;
            }
            sum += __shfl_xor_sync(0xffffffffu, sum, 1);
            sum += __shfl_xor_sync(0xffffffffu, sum, 2);
            inv[mf][hf] = 1.f / sum;
        }
    }

    // ---- Store unnormalized P (tf32) to smem, per-warp-private rows ----
#pragma unroll
    for (int mf = 0; mf < 2; ++mf) {
        int r0 = w * 32 + mf * 16 + qrow;
#pragma unroll
        for (int nf = 0; nf < 16; ++nf) {
            int jj = (nf & 3) * 8 + qc;
            char* cb = smem + pchunk_off(nf >> 2);
            uint2 p0 = {f2tf32(acc[mf][nf][0]), f2tf32(acc[mf][nf][1])};
            uint2 p1 = {f2tf32(acc[mf][nf][2]), f2tf32(acc[mf][nf][3])};
            *reinterpret_cast<uint2*>(cb + sw128(r0 * 128 + jj * 4)) = p0;
            *reinterpret_cast<uint2*>(cb + sw128((r0 + 8) * 128 + jj * 4)) = p1;
        }
    }
    __syncwarp();

    // ---- PV mma: out[32,32] per warp, 16 k-steps over j ----
    float o[2][4][4];
#pragma unroll
    for (int i = 0; i < 2; ++i)
#pragma unroll
        for (int j = 0; j < 4; ++j)
#pragma unroll
            for (int k = 0; k < 4; ++k) o[i][j][k] = 0.f;

#pragma unroll
    for (int s2 = 0; s2 < 16; ++s2) {
        const int c = s2 >> 2, ku = (s2 & 3) * 2;
        uint32_t pf[2][4];
#pragma unroll
        for (int mf = 0; mf < 2; ++mf) {
            int row = a_row_base + mf * 16;
            uint32_t addr = sb + pchunk_off(c) + row * 128 +
                            (((ku + a_us) * 16) ^ ((row & 7) * 16));
            ldsm4(pf[mf][0], pf[mf][1], pf[mf][2], pf[mf][3], addr);
        }
        uint32_t vf[4][2];
#pragma unroll
        for (int p = 0; p < 2; ++p) {
            int row = b_row_base + p * 16;   // 0..31 within Vt
            uint32_t addr = sb + ASM_VT + c * 4096 + row * 128 +
                            (((ku + b_us) * 16) ^ ((row & 7) * 16));
            ldsm4(vf[p * 2][0], vf[p * 2][1], vf[p * 2 + 1][0], vf[p * 2 + 1][1],
                  addr);
        }
#pragma unroll
        for (int mf = 0; mf < 2; ++mf)
#pragma unroll
            for (int nf = 0; nf < 4; ++nf)
                mma_tf32(o[mf][nf], pf[mf], vf[nf]);
    }

    // ---- Epilogue: normalize, store ----
    float* ob = att + (size_t)b * Nn * Cc + h * 32;
#pragma unroll
    for (int mf = 0; mf < 2; ++mf) {
        int r0 = w * 32 + mf * 16 + qrow;
#pragma unroll
        for (int nf = 0; nf < 4; ++nf) {
            int d = nf * 8 + qc;
            float2 lo = {o[mf][nf][0] * inv[mf][0], o[mf][nf][1] * inv[mf][0]};
            float2 hi = {o[mf][nf][2] * inv[mf][1], o[mf][nf][3] * inv[mf][1]};
            *reinterpret_cast<float2*>(ob + (size_t)r0 * Cc + d) = lo;
            *reinterpret_cast<float2*>(ob + (size_t)(r0 + 8) * Cc + d) = hi;
        }
    }
}

// ---------------------------------------------------------------------------
// Launch
// ---------------------------------------------------------------------------
extern "C" void kernel_launch(void* const* d_in, const int* in_sizes, int n_in,
                              void* d_out, int out_size) {
    const float* x      = (const float*)d_in[0];
    const float* mask   = (const float*)d_in[1];
    const float* qkv_w  = (const float*)d_in[2];
    const float* qkv_b  = (const float*)d_in[3];
    const float* proj_w = (const float*)d_in[4];
    const float* proj_b = (const float*)d_in[5];
    float* out = (float*)d_out;

    float *p_qkv, *p_att;
    cudaGetSymbolAddress((void**)&p_qkv, g_qkv);
    cudaGetSymbolAddress((void**)&p_att, g_att);

    cudaFuncSetAttribute(gemm_mma, cudaFuncAttributeMaxDynamicSharedMemorySize, GSM_TOTAL);
    cudaFuncSetAttribute(attn_mma, cudaFuncAttributeMaxDynamicSharedMemorySize, ATTN_SMEM_TOT);

    // 1) QKV projection (mma.sync tf32)
    gemm_mma<<<dim3(6, M_TOT / 128), 256, GSM_TOTAL>>>(x, qkv_w, qkv_b, p_qkv, 384);

    // 2) windowed attention per (b,h)  (mma.sync tf32)
    attn_mma<<<Bb * Hh, 128, ATTN_SMEM_TOT>>>(p_qkv, mask, p_att);

    // 3) output projection (mma.sync tf32)
    gemm_mma<<<dim3(2, M_TOT / 128), 256, GSM_TOTAL>>>(p_att, proj_w, proj_b, out, 128);
}

// round 5
// speedup vs baseline: 4.0979x; 1.3663x over previous
#include <cuda_runtime.h>
#include <cuda_fp16.h>
#include <cstdint>

// Problem constants
#define Bb   2048
#define Nn   128
#define Cc   128
#define Hh   4
#define NW   64
#define M_TOT (Bb * Nn)            // 262144 rows
#define SCALE 0.1767766952966369f  // 1/sqrt(32)

// ---------------------------------------------------------------------------
// Helpers (baseline ISA: ldmatrix + mma.sync fp16)
// ---------------------------------------------------------------------------
__device__ __forceinline__ uint32_t smem_u32(const void* p) {
    uint32_t a;
    asm("{ .reg .u64 t; cvta.to.shared.u64 t, %1; cvt.u32.u64 %0, t; }"
        : "=r"(a) : "l"(p));
    return a;
}
__device__ __forceinline__ uint32_t pack_h2(float a, float b) {
    __half2 h = __floats2half2_rn(a, b);
    return *reinterpret_cast<uint32_t*>(&h);
}
__device__ __forceinline__ uint32_t pack_h2_lo(float a, float b) {
    // residual after fp16 quantization (for K hi/lo split)
    float ah = __half2float(__float2half_rn(a));
    float bh = __half2float(__float2half_rn(b));
    return pack_h2(a - ah, b - bh);
}
__device__ __forceinline__ void ldsm4(uint32_t& r0, uint32_t& r1, uint32_t& r2,
                                      uint32_t& r3, uint32_t addr) {
    asm volatile("ldmatrix.sync.aligned.m8n8.x4.shared.b16 {%0,%1,%2,%3}, [%4];"
                 : "=r"(r0), "=r"(r1), "=r"(r2), "=r"(r3) : "r"(addr));
}
__device__ __forceinline__ void ldsm4t(uint32_t& r0, uint32_t& r1, uint32_t& r2,
                                       uint32_t& r3, uint32_t addr) {
    asm volatile("ldmatrix.sync.aligned.m8n8.x4.trans.shared.b16 {%0,%1,%2,%3}, [%4];"
                 : "=r"(r0), "=r"(r1), "=r"(r2), "=r"(r3) : "r"(addr));
}
__device__ __forceinline__ void mma_f16(float* c, const uint32_t* a,
                                        const uint32_t* b) {
    asm volatile(
        "mma.sync.aligned.m16n8k16.row.col.f32.f16.f16.f32 "
        "{%0,%1,%2,%3}, {%4,%5,%6,%7}, {%8,%9}, {%0,%1,%2,%3};"
        : "+f"(c[0]), "+f"(c[1]), "+f"(c[2]), "+f"(c[3])
        : "r"(a[0]), "r"(a[1]), "r"(a[2]), "r"(a[3]), "r"(b[0]), "r"(b[1]));
}

// ---------------------------------------------------------------------------
// Scratch
// ---------------------------------------------------------------------------
__device__ float  g_qkv[(size_t)M_TOT * 3 * Cc];   // [B,N,384] fp32
__device__ __half g_att[(size_t)M_TOT * Cc];       // [B,N,128] fp16

// ---------------------------------------------------------------------------
// fp16 mma.sync GEMM: out[M][Ntot] = A[M][128] @ W[Ntot][128]^T + bias
// Tile 128x64x128, 256 threads (8 warps: 4m x 2n), warp tile 32x32.
// smem: A 2 chunks x [128 rows][64 fp16 = 128B, SW128], B 2 chunks x [64][128B].
// A_HALF: A input already fp16 (proj path) vs fp32 (QKV path).
// ---------------------------------------------------------------------------
#define GSM_A     0
#define GSM_B     32768
#define GSM_TOTAL 49152

template <int A_HALF>
__global__ __launch_bounds__(256, 2)
void gemm_mma(const void* __restrict__ Ain, const float* __restrict__ W,
              const float* __restrict__ bias, float* __restrict__ out, int Ntot) {
    extern __shared__ char smem[];
    const uint32_t sA = smem_u32(smem) + GSM_A;
    const uint32_t sB = smem_u32(smem) + GSM_B;
    const int tid  = threadIdx.x;
    const int wid  = tid >> 5;
    const int lane = tid & 31;
    const int nBase = blockIdx.x * 64;
    const int mBase = blockIdx.y * 128;
    const int wm = wid & 3;
    const int wn = wid >> 2;

    // ---- A tile -> smem fp16 (2048 x 16B units; unit g: k = g*8..g*8+7) ----
    if (A_HALF) {
        const __half* A16 = (const __half*)Ain + (size_t)mBase * 128;
#pragma unroll
        for (int it = 0; it < 8; ++it) {
            int idx = it * 256 + tid;
            int m = idx >> 4, g = idx & 15;
            uint4 v = reinterpret_cast<const uint4*>(A16 + (size_t)m * 128)[g];
            *reinterpret_cast<uint4*>(
                (char*)smem + GSM_A + (g >> 3) * 16384 + m * 128 +
                16 * ((g & 7) ^ (m & 7))) = v;
        }
    } else {
        const float4* A4 = reinterpret_cast<const float4*>((const float*)Ain +
                                                           (size_t)mBase * 128);
#pragma unroll
        for (int it = 0; it < 8; ++it) {
            int idx = it * 256 + tid;
            int m = idx >> 4, g = idx & 15;
            float4 a = A4[(size_t)m * 32 + g * 2];
            float4 b = A4[(size_t)m * 32 + g * 2 + 1];
            uint4 u = {pack_h2(a.x, a.y), pack_h2(a.z, a.w),
                       pack_h2(b.x, b.y), pack_h2(b.z, b.w)};
            *reinterpret_cast<uint4*>(
                (char*)smem + GSM_A + (g >> 3) * 16384 + m * 128 +
                16 * ((g & 7) ^ (m & 7))) = u;
        }
    }
    // ---- B tile (weights fp32 -> fp16) ----
    {
        const float4* B4 = reinterpret_cast<const float4*>(W + (size_t)nBase * 128);
#pragma unroll
        for (int it = 0; it < 4; ++it) {
            int idx = it * 256 + tid;
            int n = idx >> 4, g = idx & 15;
            float4 a = B4[(size_t)n * 32 + g * 2];
            float4 b = B4[(size_t)n * 32 + g * 2 + 1];
            uint4 u = {pack_h2(a.x, a.y), pack_h2(a.z, a.w),
                       pack_h2(b.x, b.y), pack_h2(b.z, b.w)};
            *reinterpret_cast<uint4*>(
                (char*)smem + GSM_B + (g >> 3) * 8192 + n * 128 +
                16 * ((g & 7) ^ (n & 7))) = u;
        }
    }
    __syncthreads();

    const int r8 = lane & 7, t = lane >> 3;
    const int a_row0 = wm * 32 + (t & 1) * 8 + r8;
    const int a_us   = t >> 1;
    const int b_row0 = wn * 32 + (t >> 1) * 8 + r8;
    const int b_us   = t & 1;

    float acc[2][4][4];
#pragma unroll
    for (int i = 0; i < 2; ++i)
#pragma unroll
        for (int j = 0; j < 4; ++j)
#pragma unroll
            for (int k = 0; k < 4; ++k) acc[i][j][k] = 0.f;

    // ---- Mainloop: 8 k-steps of k=16 ----
#pragma unroll
    for (int s = 0; s < 8; ++s) {
        const int c = s >> 2;
        const int ku = (s & 3) * 2;
        uint32_t af[2][4], bf[4][2];
#pragma unroll
        for (int mf = 0; mf < 2; ++mf) {
            int row = a_row0 + mf * 16;
            uint32_t addr = sA + c * 16384 + row * 128 +
                            (((ku + a_us) * 16) ^ ((row & 7) * 16));
            ldsm4(af[mf][0], af[mf][1], af[mf][2], af[mf][3], addr);
        }
#pragma unroll
        for (int p = 0; p < 2; ++p) {
            int row = b_row0 + p * 16;
            uint32_t addr = sB + c * 8192 + row * 128 +
                            (((ku + b_us) * 16) ^ ((row & 7) * 16));
            ldsm4(bf[p * 2][0], bf[p * 2][1], bf[p * 2 + 1][0], bf[p * 2 + 1][1],
                  addr);
        }
#pragma unroll
        for (int mf = 0; mf < 2; ++mf)
#pragma unroll
            for (int nf = 0; nf < 4; ++nf)
                mma_f16(acc[mf][nf], af[mf], bf[nf]);
    }

    // ---- Epilogue: + bias ----
#pragma unroll
    for (int mf = 0; mf < 2; ++mf) {
        const int rowg = mBase + wm * 32 + mf * 16 + (lane >> 2);
#pragma unroll
        for (int nf = 0; nf < 4; ++nf) {
            const int col = nBase + wn * 32 + nf * 8 + (lane & 3) * 2;
            float2 bv = *reinterpret_cast<const float2*>(&bias[col]);
            float2 o0 = {acc[mf][nf][0] + bv.x, acc[mf][nf][1] + bv.y};
            float2 o1 = {acc[mf][nf][2] + bv.x, acc[mf][nf][3] + bv.y};
            *reinterpret_cast<float2*>(out + (size_t)rowg * Ntot + col) = o0;
            *reinterpret_cast<float2*>(out + (size_t)(rowg + 8) * Ntot + col) = o1;
        }
    }
}

// ---------------------------------------------------------------------------
// fp16 tensor-core attention: block per (b,h), 4 warps, warp w owns 32 q-rows.
// S = (Q*SCALE)@K^T + mask  (K hi/lo fp16 split), register softmax,
// P fp16 -> smem (overlaying Q/Khi/Klo), PV fp16 (V via ldmatrix.trans).
// Rows of 32 fp16 = 64B; 2 logical rows packed per 128B physical row, SW128.
// smem: Q 8K | Khi 8K | Klo 8K | V 8K | P3 8K = 40KB -> 3 CTAs/SM.
// ---------------------------------------------------------------------------
#define ASM_Q    0
#define ASM_KHI  8192
#define ASM_KLO  16384
#define ASM_V    24576
#define ASM_P3   32768
#define ATTN_SMEM_TOT 40960

__device__ __forceinline__ uint32_t pchunk_off(int c) {
    return (c == 3) ? (uint32_t)ASM_P3 : (uint32_t)(c * 8192);
}
// packed-row address: logical row r (64B rows), unit u (0..3)
__device__ __forceinline__ uint32_t prow_addr(int r, int u) {
    return (uint32_t)((r >> 1) * 128 + 16 * ((((r & 1) * 4) + u) ^ ((r >> 1) & 7)));
}

__global__ __launch_bounds__(128, 3)
void attn_mma(const float* __restrict__ qkv, const float* __restrict__ mask,
              __half* __restrict__ att) {
    extern __shared__ char smem[];
    const uint32_t sb = smem_u32(smem);
    const int tid = threadIdx.x, lane = tid & 31, w = tid >> 5;
    const int bh = blockIdx.x, b = bh >> 2, h = bh & 3, win = b & (NW - 1);
    const float* base  = qkv + (size_t)b * Nn * 384;
    const float* mbase = mask + (size_t)win * Nn * Nn;

    const int qrow = lane >> 2;        // 0..7
    const int qc   = (lane & 3) * 2;   // 0,2,4,6

    // ---- Load Q(scaled), K hi/lo, V into smem as fp16 ----
    {
        const float4* qr = reinterpret_cast<const float4*>(base + (size_t)tid * 384 + h * 32);
        const float4* kr = reinterpret_cast<const float4*>(base + (size_t)tid * 384 + 128 + h * 32);
        const float4* vr = reinterpret_cast<const float4*>(base + (size_t)tid * 384 + 256 + h * 32);
#pragma unroll
        for (int u = 0; u < 4; ++u) {
            uint32_t so = prow_addr(tid, u);

            float4 a = qr[u * 2], c = qr[u * 2 + 1];
            uint4 qs = {pack_h2(a.x * SCALE, a.y * SCALE), pack_h2(a.z * SCALE, a.w * SCALE),
                        pack_h2(c.x * SCALE, c.y * SCALE), pack_h2(c.z * SCALE, c.w * SCALE)};
            *reinterpret_cast<uint4*>(smem + ASM_Q + so) = qs;

            float4 ka = kr[u * 2], kc = kr[u * 2 + 1];
            uint4 kh = {pack_h2(ka.x, ka.y), pack_h2(ka.z, ka.w),
                        pack_h2(kc.x, kc.y), pack_h2(kc.z, kc.w)};
            uint4 kl = {pack_h2_lo(ka.x, ka.y), pack_h2_lo(ka.z, ka.w),
                        pack_h2_lo(kc.x, kc.y), pack_h2_lo(kc.z, kc.w)};
            *reinterpret_cast<uint4*>(smem + ASM_KHI + so) = kh;
            *reinterpret_cast<uint4*>(smem + ASM_KLO + so) = kl;

            float4 va = vr[u * 2], vc = vr[u * 2 + 1];
            uint4 vs = {pack_h2(va.x, va.y), pack_h2(va.z, va.w),
                        pack_h2(vc.x, vc.y), pack_h2(vc.z, vc.w)};
            *reinterpret_cast<uint4*>(smem + ASM_V + so) = vs;
        }
    }

    // ---- Accumulators initialized from mask ----
    float acc[2][16][4];
#pragma unroll
    for (int mf = 0; mf < 2; ++mf) {
        const float* mr = mbase + (w * 32 + mf * 16 + qrow) * Nn + qc;
#pragma unroll
        for (int nf = 0; nf < 16; ++nf) {
            float2 m0 = *reinterpret_cast<const float2*>(mr + nf * 8);
            float2 m1 = *reinterpret_cast<const float2*>(mr + 8 * Nn + nf * 8);
            acc[mf][nf][0] = m0.x; acc[mf][nf][1] = m0.y;
            acc[mf][nf][2] = m1.x; acc[mf][nf][3] = m1.y;
        }
    }
    __syncthreads();

    const int r8 = lane & 7, t4 = lane >> 3;
    const int a_us = t4 >> 1, b_us = t4 & 1;
    const int a_row0 = w * 32 + (t4 & 1) * 8 + r8;
    const int b_roff = (t4 >> 1) * 8 + r8;

    // ---- S mma: 2 k-steps (hd=32, k16), K as hi+lo ----
#pragma unroll
    for (int s = 0; s < 2; ++s) {
        const int ku = s * 2;
        uint32_t qf[2][4];
#pragma unroll
        for (int mf = 0; mf < 2; ++mf) {
            uint32_t addr = sb + ASM_Q + prow_addr(a_row0 + mf * 16, ku + a_us);
            ldsm4(qf[mf][0], qf[mf][1], qf[mf][2], qf[mf][3], addr);
        }
#pragma unroll
        for (int p = 0; p < 8; ++p) {
            uint32_t off = prow_addr(p * 16 + b_roff, ku + b_us);
            uint32_t kh[2][2], kl[2][2];
            ldsm4(kh[0][0], kh[0][1], kh[1][0], kh[1][1], sb + ASM_KHI + off);
            ldsm4(kl[0][0], kl[0][1], kl[1][0], kl[1][1], sb + ASM_KLO + off);
#pragma unroll
            for (int mf = 0; mf < 2; ++mf) {
#pragma unroll
                for (int e = 0; e < 2; ++e) {
                    mma_f16(acc[mf][p * 2 + e], qf[mf], kh[e]);
                    mma_f16(acc[mf][p * 2 + e], qf[mf], kl[e]);
                }
            }
        }
    }
    __syncthreads();   // all warps done reading Q/K before P overwrites

    // ---- Register softmax ----
    float inv[2][2];
#pragma unroll
    for (int mf = 0; mf < 2; ++mf) {
#pragma unroll
        for (int hf = 0; hf < 2; ++hf) {
            float mx = -1e30f;
#pragma unroll
            for (int nf = 0; nf < 16; ++nf)
                mx = fmaxf(mx, fmaxf(acc[mf][nf][hf * 2], acc[mf][nf][hf * 2 + 1]));
            mx = fmaxf(mx, __shfl_xor_sync(0xffffffffu, mx, 1));
            mx = fmaxf(mx, __shfl_xor_sync(0xffffffffu, mx, 2));
            float sum = 0.f;
#pragma unroll
            for (int nf = 0; nf < 16; ++nf) {
                float e0 = __expf(acc[mf][nf][hf * 2] - mx);
                float e1 = __expf(acc[mf][nf][hf * 2 + 1] - mx);
                acc[mf][nf][hf * 2] = e0;
                acc[mf][nf][hf * 2 + 1] = e1;
                sum += e0 + e1;
            }
            sum += __shfl_xor_sync(0xffffffffu, sum, 1);
            sum += __shfl_xor_sync(0xffffffffu, sum, 2);
            inv[mf][hf] = 1.f / sum;
        }
    }

    // ---- Store unnormalized P (fp16) to smem, warp-private rows ----
#pragma unroll
    for (int mf = 0; mf < 2; ++mf) {
        int r0 = w * 32 + mf * 16 + qrow;
#pragma unroll
        for (int nf = 0; nf < 16; ++nf) {
            int c = nf >> 2;
            int un = nf & 3;                 // unit within chunk (qc < 8)
            uint32_t a0 = sb + pchunk_off(c) + prow_addr(r0, un) + qc * 2;
            uint32_t a1 = sb + pchunk_off(c) + prow_addr(r0 + 8, un) + qc * 2;
            uint32_t p0 = pack_h2(acc[mf][nf][0], acc[mf][nf][1]);
            uint32_t p1 = pack_h2(acc[mf][nf][2], acc[mf][nf][3]);
            asm volatile("st.shared.b32 [%0], %1;" :: "r"(a0), "r"(p0) : "memory");
            asm volatile("st.shared.b32 [%0], %1;" :: "r"(a1), "r"(p1) : "memory");
        }
    }
    __syncwarp();

    // ---- PV mma: 8 k-steps (k16 over j), V via ldmatrix.trans ----
    float o[2][4][4];
#pragma unroll
    for (int i = 0; i < 2; ++i)
#pragma unroll
        for (int j = 0; j < 4; ++j)
#pragma unroll
            for (int k = 0; k < 4; ++k) o[i][j][k] = 0.f;

#pragma unroll
    for (int s2 = 0; s2 < 8; ++s2) {
        const int c = s2 >> 1, kk2 = (s2 & 1) * 2;
        uint32_t pf[2][4];
#pragma unroll
        for (int mf = 0; mf < 2; ++mf) {
            uint32_t addr = sb + pchunk_off(c) +
                            prow_addr(a_row0 + mf * 16, kk2 + a_us);
            ldsm4(pf[mf][0], pf[mf][1], pf[mf][2], pf[mf][3], addr);
        }
        uint32_t vf[4][2];
        const int jrow = c * 32 + (s2 & 1) * 16 + (t4 & 1) * 8 + r8;
#pragma unroll
        for (int nu = 0; nu < 2; ++nu) {
            uint32_t addr = sb + ASM_V + prow_addr(jrow, nu * 2 + (t4 >> 1));
            ldsm4t(vf[nu * 2][0], vf[nu * 2][1], vf[nu * 2 + 1][0],
                   vf[nu * 2 + 1][1], addr);
        }
#pragma unroll
        for (int mf = 0; mf < 2; ++mf)
#pragma unroll
            for (int nf = 0; nf < 4; ++nf)
                mma_f16(o[mf][nf], pf[mf], vf[nf]);
    }

    // ---- Epilogue: normalize, store fp16 att ----
    __half* ob = att + (size_t)b * Nn * Cc + h * 32;
#pragma unroll
    for (int mf = 0; mf < 2; ++mf) {
        int r0 = w * 32 + mf * 16 + qrow;
#pragma unroll
        for (int nf = 0; nf < 4; ++nf) {
            int d = nf * 8 + qc;
            uint32_t lo = pack_h2(o[mf][nf][0] * inv[mf][0], o[mf][nf][1] * inv[mf][0]);
            uint32_t hi = pack_h2(o[mf][nf][2] * inv[mf][1], o[mf][nf][3] * inv[mf][1]);
            *reinterpret_cast<uint32_t*>(ob + (size_t)r0 * Cc + d) = lo;
            *reinterpret_cast<uint32_t*>(ob + (size_t)(r0 + 8) * Cc + d) = hi;
        }
    }
}

// ---------------------------------------------------------------------------
// Launch
// ---------------------------------------------------------------------------
extern "C" void kernel_launch(void* const* d_in, const int* in_sizes, int n_in,
                              void* d_out, int out_size) {
    const float* x      = (const float*)d_in[0];
    const float* mask   = (const float*)d_in[1];
    const float* qkv_w  = (const float*)d_in[2];
    const float* qkv_b  = (const float*)d_in[3];
    const float* proj_w = (const float*)d_in[4];
    const float* proj_b = (const float*)d_in[5];
    float* out = (float*)d_out;

    float  *p_qkv;
    __half *p_att;
    cudaGetSymbolAddress((void**)&p_qkv, g_qkv);
    cudaGetSymbolAddress((void**)&p_att, g_att);

    cudaFuncSetAttribute(gemm_mma<0>, cudaFuncAttributeMaxDynamicSharedMemorySize, GSM_TOTAL);
    cudaFuncSetAttribute(gemm_mma<1>, cudaFuncAttributeMaxDynamicSharedMemorySize, GSM_TOTAL);
    cudaFuncSetAttribute(attn_mma, cudaFuncAttributeMaxDynamicSharedMemorySize, ATTN_SMEM_TOT);

    // 1) QKV projection (fp16 mma.sync)
    gemm_mma<0><<<dim3(6, M_TOT / 128), 256, GSM_TOTAL>>>(x, qkv_w, qkv_b, p_qkv, 384);

    // 2) windowed attention per (b,h)  (fp16 mma.sync)
    attn_mma<<<Bb * Hh, 128, ATTN_SMEM_TOT>>>(p_qkv, mask, p_att);

    // 3) output projection (fp16 mma.sync, fp16 A input)
    gemm_mma<1><<<dim3(2, M_TOT / 128), 256, GSM_TOTAL>>>(p_att, proj_w, proj_b, out, 128);
}

// round 6
// speedup vs baseline: 4.9590x; 1.2101x over previous
#include <cuda_runtime.h>
#include <cuda_fp16.h>
#include <cstdint>

// Problem constants
#define Bb   2048
#define Nn   128
#define Cc   128
#define Hh   4
#define NW   64
#define M_TOT (Bb * Nn)            // 262144 rows
#define SCALE 0.1767766952966369f  // 1/sqrt(32)

// ---------------------------------------------------------------------------
// Helpers (baseline ISA: ldmatrix + mma.sync fp16)
// ---------------------------------------------------------------------------
__device__ __forceinline__ uint32_t smem_u32(const void* p) {
    uint32_t a;
    asm("{ .reg .u64 t; cvta.to.shared.u64 t, %1; cvt.u32.u64 %0, t; }"
        : "=r"(a) : "l"(p));
    return a;
}
__device__ __forceinline__ uint32_t pack_h2(float a, float b) {
    __half2 h = __floats2half2_rn(a, b);
    return *reinterpret_cast<uint32_t*>(&h);
}
__device__ __forceinline__ uint32_t pack_h2_lo(float a, float b) {
    float ah = __half2float(__float2half_rn(a));
    float bh = __half2float(__float2half_rn(b));
    return pack_h2(a - ah, b - bh);
}
__device__ __forceinline__ void ldsm4(uint32_t& r0, uint32_t& r1, uint32_t& r2,
                                      uint32_t& r3, uint32_t addr) {
    asm volatile("ldmatrix.sync.aligned.m8n8.x4.shared.b16 {%0,%1,%2,%3}, [%4];"
                 : "=r"(r0), "=r"(r1), "=r"(r2), "=r"(r3) : "r"(addr));
}
__device__ __forceinline__ void ldsm4t(uint32_t& r0, uint32_t& r1, uint32_t& r2,
                                       uint32_t& r3, uint32_t addr) {
    asm volatile("ldmatrix.sync.aligned.m8n8.x4.trans.shared.b16 {%0,%1,%2,%3}, [%4];"
                 : "=r"(r0), "=r"(r1), "=r"(r2), "=r"(r3) : "r"(addr));
}
__device__ __forceinline__ void mma_f16(float* c, const uint32_t* a,
                                        const uint32_t* b) {
    asm volatile(
        "mma.sync.aligned.m16n8k16.row.col.f32.f16.f16.f32 "
        "{%0,%1,%2,%3}, {%4,%5,%6,%7}, {%8,%9}, {%0,%1,%2,%3};"
        : "+f"(c[0]), "+f"(c[1]), "+f"(c[2]), "+f"(c[3])
        : "r"(a[0]), "r"(a[1]), "r"(a[2]), "r"(a[3]), "r"(b[0]), "r"(b[1]));
}

// ---------------------------------------------------------------------------
// Scratch
// ---------------------------------------------------------------------------
__device__ __half g_q16[(size_t)M_TOT * 3 * Cc];   // [B,N,384] fp16 (q pre-scaled, k=hi, v)
__device__ __half g_klo[(size_t)M_TOT * Cc];       // [B,N,128] fp16 K residual
__device__ __half g_att[(size_t)M_TOT * Cc];       // [B,N,128] fp16
__device__ __half g_w16[3 * Cc * Cc];              // qkv_w fp16
__device__ __half g_pw16[Cc * Cc];                 // proj_w fp16
__device__ __half g_mask16[NW * Nn * Nn];          // mask fp16

// ---------------------------------------------------------------------------
// Prepass: weights + mask -> fp16 (float2 -> half2)
// ---------------------------------------------------------------------------
#define MASK2  (NW * Nn * Nn / 2)          // 524288
#define QW2    (3 * Cc * Cc / 2)           // 24576
#define PW2    (Cc * Cc / 2)               // 8192
#define PREP_TOT (MASK2 + QW2 + PW2)

__global__ void prep16(const float* __restrict__ mask,
                       const float* __restrict__ qkv_w,
                       const float* __restrict__ proj_w) {
    int idx = blockIdx.x * blockDim.x + threadIdx.x;
    if (idx >= PREP_TOT) return;
    if (idx < MASK2) {
        float2 v = reinterpret_cast<const float2*>(mask)[idx];
        reinterpret_cast<uint32_t*>(g_mask16)[idx] = pack_h2(v.x, v.y);
    } else if (idx < MASK2 + QW2) {
        float2 v = reinterpret_cast<const float2*>(qkv_w)[idx - MASK2];
        reinterpret_cast<uint32_t*>(g_w16)[idx - MASK2] = pack_h2(v.x, v.y);
    } else {
        float2 v = reinterpret_cast<const float2*>(proj_w)[idx - MASK2 - QW2];
        reinterpret_cast<uint32_t*>(g_pw16)[idx - MASK2 - QW2] = pack_h2(v.x, v.y);
    }
}

// ---------------------------------------------------------------------------
// fp16 mma.sync GEMM v2: CTA tile 128x128xK128, 8 warps (4m x 2n), warp 32x64.
// smem: A 2 chunks x [128][64 fp16 =128B SW128] 32KB, B same 32KB -> 64KB.
// MODE 0: QKV path — A fp32 LDG, outputs fp16 to g_q16 (+klo residual),
//         q section pre-scaled by SCALE.
// MODE 1: proj path — A fp16 LDG (g_att), out fp32 + bias.
// B always fp16 (prepass).
// ---------------------------------------------------------------------------
#define GSM_A     0
#define GSM_B     32768
#define GSM_TOTAL 65536

template <int MODE>
__global__ __launch_bounds__(256, 2)
void gemm_mma(const void* __restrict__ Ain, const __half* __restrict__ W16,
              const float* __restrict__ bias, float* __restrict__ out) {
    extern __shared__ char smem[];
    const uint32_t sA = smem_u32(smem) + GSM_A;
    const uint32_t sB = smem_u32(smem) + GSM_B;
    const int tid  = threadIdx.x;
    const int wid  = tid >> 5;
    const int lane = tid & 31;
    const int nBase = blockIdx.x * 128;
    const int mBase = blockIdx.y * 128;
    const int wm = wid & 3;      // 32 rows each
    const int wn = wid >> 2;     // 64 cols each

    // ---- A tile -> smem fp16 ----
    if (MODE == 1) {
        const __half* A16 = (const __half*)Ain + (size_t)mBase * 128;
#pragma unroll
        for (int it = 0; it < 8; ++it) {
            int idx = it * 256 + tid;
            int m = idx >> 4, g = idx & 15;
            uint4 v = reinterpret_cast<const uint4*>(A16 + (size_t)m * 128)[g];
            *reinterpret_cast<uint4*>(
                (char*)smem + GSM_A + (g >> 3) * 16384 + m * 128 +
                16 * ((g & 7) ^ (m & 7))) = v;
        }
    } else {
        const float4* A4 = reinterpret_cast<const float4*>((const float*)Ain +
                                                           (size_t)mBase * 128);
#pragma unroll
        for (int it = 0; it < 8; ++it) {
            int idx = it * 256 + tid;
            int m = idx >> 4, g = idx & 15;
            float4 a = A4[(size_t)m * 32 + g * 2];
            float4 b = A4[(size_t)m * 32 + g * 2 + 1];
            uint4 u = {pack_h2(a.x, a.y), pack_h2(a.z, a.w),
                       pack_h2(b.x, b.y), pack_h2(b.z, b.w)};
            *reinterpret_cast<uint4*>(
                (char*)smem + GSM_A + (g >> 3) * 16384 + m * 128 +
                16 * ((g & 7) ^ (m & 7))) = u;
        }
    }
    // ---- B tile (fp16 weights, straight swizzled copy) ----
    {
        const __half* Bp = W16 + (size_t)nBase * 128;
#pragma unroll
        for (int it = 0; it < 8; ++it) {
            int idx = it * 256 + tid;
            int n = idx >> 4, g = idx & 15;
            uint4 v = reinterpret_cast<const uint4*>(Bp + (size_t)n * 128)[g];
            *reinterpret_cast<uint4*>(
                (char*)smem + GSM_B + (g >> 3) * 16384 + n * 128 +
                16 * ((g & 7) ^ (n & 7))) = v;
        }
    }
    __syncthreads();

    const int r8 = lane & 7, t = lane >> 3;
    const int a_row0 = wm * 32 + (t & 1) * 8 + r8;
    const int a_us   = t >> 1;
    const int b_roff = (t >> 1) * 8 + r8;
    const int b_us   = t & 1;

    float acc[2][8][4];
#pragma unroll
    for (int i = 0; i < 2; ++i)
#pragma unroll
        for (int j = 0; j < 8; ++j)
#pragma unroll
            for (int k = 0; k < 4; ++k) acc[i][j][k] = 0.f;

    // ---- Mainloop: 8 k-steps of k=16 ----
#pragma unroll
    for (int s = 0; s < 8; ++s) {
        const int c = s >> 2;
        const int ku = (s & 3) * 2;
        uint32_t af[2][4], bf[8][2];
#pragma unroll
        for (int mf = 0; mf < 2; ++mf) {
            int row = a_row0 + mf * 16;
            uint32_t addr = sA + c * 16384 + row * 128 +
                            (((ku + a_us) * 16) ^ ((row & 7) * 16));
            ldsm4(af[mf][0], af[mf][1], af[mf][2], af[mf][3], addr);
        }
#pragma unroll
        for (int p = 0; p < 4; ++p) {
            int row = wn * 64 + p * 16 + b_roff;
            uint32_t addr = sB + c * 16384 + row * 128 +
                            (((ku + b_us) * 16) ^ ((row & 7) * 16));
            ldsm4(bf[p * 2][0], bf[p * 2][1], bf[p * 2 + 1][0], bf[p * 2 + 1][1],
                  addr);
        }
#pragma unroll
        for (int mf = 0; mf < 2; ++mf)
#pragma unroll
            for (int nf = 0; nf < 8; ++nf)
                mma_f16(acc[mf][nf], af[mf], bf[nf]);
    }

    // ---- Epilogue ----
    const int qrow = lane >> 2, qc = (lane & 3) * 2;
    if (MODE == 1) {
#pragma unroll
        for (int mf = 0; mf < 2; ++mf) {
            const int rowg = mBase + wm * 32 + mf * 16 + qrow;
#pragma unroll
            for (int nf = 0; nf < 8; ++nf) {
                const int col = nBase + wn * 64 + nf * 8 + qc;
                float2 bv = *reinterpret_cast<const float2*>(&bias[col]);
                float2 o0 = {acc[mf][nf][0] + bv.x, acc[mf][nf][1] + bv.y};
                float2 o1 = {acc[mf][nf][2] + bv.x, acc[mf][nf][3] + bv.y};
                *reinterpret_cast<float2*>(out + (size_t)rowg * 128 + col) = o0;
                *reinterpret_cast<float2*>(out + (size_t)(rowg + 8) * 128 + col) = o1;
            }
        }
    } else {
        // QKV: fp16 outputs. nBase selects section: 0=q (scaled), 128=k (hi+lo), 256=v.
#pragma unroll
        for (int mf = 0; mf < 2; ++mf) {
            const size_t r0 = (size_t)mBase + wm * 32 + mf * 16 + qrow;
#pragma unroll
            for (int nf = 0; nf < 8; ++nf) {
                const int col = nBase + wn * 64 + nf * 8 + qc;
                float2 bv = *reinterpret_cast<const float2*>(&bias[col]);
                float v00 = acc[mf][nf][0] + bv.x, v01 = acc[mf][nf][1] + bv.y;
                float v10 = acc[mf][nf][2] + bv.x, v11 = acc[mf][nf][3] + bv.y;
                __half* o0 = g_q16 + r0 * 384 + col;
                __half* o1 = o0 + (size_t)8 * 384;
                if (nBase == 0) {
                    *reinterpret_cast<uint32_t*>(o0) = pack_h2(v00 * SCALE, v01 * SCALE);
                    *reinterpret_cast<uint32_t*>(o1) = pack_h2(v10 * SCALE, v11 * SCALE);
                } else if (nBase == 128) {
                    *reinterpret_cast<uint32_t*>(o0) = pack_h2(v00, v01);
                    *reinterpret_cast<uint32_t*>(o1) = pack_h2(v10, v11);
                    __half* l0 = g_klo + r0 * 128 + (col - 128);
                    __half* l1 = l0 + (size_t)8 * 128;
                    *reinterpret_cast<uint32_t*>(l0) = pack_h2_lo(v00, v01);
                    *reinterpret_cast<uint32_t*>(l1) = pack_h2_lo(v10, v11);
                } else {
                    *reinterpret_cast<uint32_t*>(o0) = pack_h2(v00, v01);
                    *reinterpret_cast<uint32_t*>(o1) = pack_h2(v10, v11);
                }
            }
        }
    }
}

// ---------------------------------------------------------------------------
// fp16 tensor-core attention (round-5 structure, fp16 inputs, no cvts)
// smem: Q 8K | Khi 8K | Klo 8K | V 8K | P3 8K = 40KB -> 3 CTAs/SM.
// ---------------------------------------------------------------------------
#define ASM_Q    0
#define ASM_KHI  8192
#define ASM_KLO  16384
#define ASM_V    24576
#define ASM_P3   32768
#define ATTN_SMEM_TOT 40960

__device__ __forceinline__ uint32_t pchunk_off(int c) {
    return (c == 3) ? (uint32_t)ASM_P3 : (uint32_t)(c * 8192);
}
__device__ __forceinline__ uint32_t prow_addr(int r, int u) {
    return (uint32_t)((r >> 1) * 128 + 16 * ((((r & 1) * 4) + u) ^ ((r >> 1) & 7)));
}

__global__ __launch_bounds__(128, 3)
void attn_mma(const __half* __restrict__ qkv16, const __half* __restrict__ klo,
              const __half* __restrict__ mask16, __half* __restrict__ att) {
    extern __shared__ char smem[];
    const uint32_t sb = smem_u32(smem);
    const int tid = threadIdx.x, lane = tid & 31, w = tid >> 5;
    const int bh = blockIdx.x, b = bh >> 2, h = bh & 3, win = b & (NW - 1);
    const __half* base = qkv16 + (size_t)b * Nn * 384;
    const __half* lbase = klo + (size_t)b * Nn * 128;
    const __half* mbase = mask16 + (size_t)win * Nn * Nn;

    const int qrow = lane >> 2;        // 0..7
    const int qc   = (lane & 3) * 2;   // 0,2,4,6

    // ---- Load q (pre-scaled), khi, klo, v: straight fp16 uint4 copies ----
    {
        const uint4* qr = reinterpret_cast<const uint4*>(base + (size_t)tid * 384 + h * 32);
        const uint4* kr = reinterpret_cast<const uint4*>(base + (size_t)tid * 384 + 128 + h * 32);
        const uint4* vr = reinterpret_cast<const uint4*>(base + (size_t)tid * 384 + 256 + h * 32);
        const uint4* lr = reinterpret_cast<const uint4*>(lbase + (size_t)tid * 128 + h * 32);
#pragma unroll
        for (int u = 0; u < 4; ++u) {
            uint32_t so = prow_addr(tid, u);
            *reinterpret_cast<uint4*>(smem + ASM_Q + so)   = qr[u];
            *reinterpret_cast<uint4*>(smem + ASM_KHI + so) = kr[u];
            *reinterpret_cast<uint4*>(smem + ASM_KLO + so) = lr[u];
            *reinterpret_cast<uint4*>(smem + ASM_V + so)   = vr[u];
        }
    }

    // ---- Accumulators initialized from fp16 mask ----
    float acc[2][16][4];
#pragma unroll
    for (int mf = 0; mf < 2; ++mf) {
        const __half* mr = mbase + (w * 32 + mf * 16 + qrow) * Nn + qc;
#pragma unroll
        for (int nf = 0; nf < 16; ++nf) {
            __half2 m0 = *reinterpret_cast<const __half2*>(mr + nf * 8);
            __half2 m1 = *reinterpret_cast<const __half2*>(mr + 8 * Nn + nf * 8);
            float2 f0 = __half22float2(m0);
            float2 f1 = __half22float2(m1);
            acc[mf][nf][0] = f0.x; acc[mf][nf][1] = f0.y;
            acc[mf][nf][2] = f1.x; acc[mf][nf][3] = f1.y;
        }
    }
    __syncthreads();

    const int r8 = lane & 7, t4 = lane >> 3;
    const int a_us = t4 >> 1, b_us = t4 & 1;
    const int a_row0 = w * 32 + (t4 & 1) * 8 + r8;
    const int b_roff = (t4 >> 1) * 8 + r8;

    // ---- S mma: 2 k-steps (hd=32, k16), K = hi + lo ----
#pragma unroll
    for (int s = 0; s < 2; ++s) {
        const int ku = s * 2;
        uint32_t qf[2][4];
#pragma unroll
        for (int mf = 0; mf < 2; ++mf) {
            uint32_t addr = sb + ASM_Q + prow_addr(a_row0 + mf * 16, ku + a_us);
            ldsm4(qf[mf][0], qf[mf][1], qf[mf][2], qf[mf][3], addr);
        }
#pragma unroll
        for (int p = 0; p < 8; ++p) {
            uint32_t off = prow_addr(p * 16 + b_roff, ku + b_us);
            uint32_t kh[2][2], kl[2][2];
            ldsm4(kh[0][0], kh[0][1], kh[1][0], kh[1][1], sb + ASM_KHI + off);
            ldsm4(kl[0][0], kl[0][1], kl[1][0], kl[1][1], sb + ASM_KLO + off);
#pragma unroll
            for (int mf = 0; mf < 2; ++mf) {
#pragma unroll
                for (int e = 0; e < 2; ++e) {
                    mma_f16(acc[mf][p * 2 + e], qf[mf], kh[e]);
                    mma_f16(acc[mf][p * 2 + e], qf[mf], kl[e]);
                }
            }
        }
    }
    __syncthreads();   // all warps done reading Q/K before P overwrites

    // ---- Register softmax ----
    float inv[2][2];
#pragma unroll
    for (int mf = 0; mf < 2; ++mf) {
#pragma unroll
        for (int hf = 0; hf < 2; ++hf) {
            float mx = -1e30f;
#pragma unroll
            for (int nf = 0; nf < 16; ++nf)
                mx = fmaxf(mx, fmaxf(acc[mf][nf][hf * 2], acc[mf][nf][hf * 2 + 1]));
            mx = fmaxf(mx, __shfl_xor_sync(0xffffffffu, mx, 1));
            mx = fmaxf(mx, __shfl_xor_sync(0xffffffffu, mx, 2));
            float sum = 0.f;
#pragma unroll
            for (int nf = 0; nf < 16; ++nf) {
                float e0 = __expf(acc[mf][nf][hf * 2] - mx);
                float e1 = __expf(acc[mf][nf][hf * 2 + 1] - mx);
                acc[mf][nf][hf * 2] = e0;
                acc[mf][nf][hf * 2 + 1] = e1;
                sum += e0 + e1;
            }
            sum += __shfl_xor_sync(0xffffffffu, sum, 1);
            sum += __shfl_xor_sync(0xffffffffu, sum, 2);
            inv[mf][hf] = 1.f / sum;
        }
    }

    // ---- Store unnormalized P (fp16) to smem, warp-private rows ----
#pragma unroll
    for (int mf = 0; mf < 2; ++mf) {
        int r0 = w * 32 + mf * 16 + qrow;
#pragma unroll
        for (int nf = 0; nf < 16; ++nf) {
            int c = nf >> 2;
            int un = nf & 3;
            uint32_t a0 = sb + pchunk_off(c) + prow_addr(r0, un) + qc * 2;
            uint32_t a1 = sb + pchunk_off(c) + prow_addr(r0 + 8, un) + qc * 2;
            uint32_t p0 = pack_h2(acc[mf][nf][0], acc[mf][nf][1]);
            uint32_t p1 = pack_h2(acc[mf][nf][2], acc[mf][nf][3]);
            asm volatile("st.shared.b32 [%0], %1;" :: "r"(a0), "r"(p0) : "memory");
            asm volatile("st.shared.b32 [%0], %1;" :: "r"(a1), "r"(p1) : "memory");
        }
    }
    __syncwarp();

    // ---- PV mma: 8 k-steps (k16 over j), V via ldmatrix.trans ----
    float o[2][4][4];
#pragma unroll
    for (int i = 0; i < 2; ++i)
#pragma unroll
        for (int j = 0; j < 4; ++j)
#pragma unroll
            for (int k = 0; k < 4; ++k) o[i][j][k] = 0.f;

#pragma unroll
    for (int s2 = 0; s2 < 8; ++s2) {
        const int c = s2 >> 1, kk2 = (s2 & 1) * 2;
        uint32_t pf[2][4];
#pragma unroll
        for (int mf = 0; mf < 2; ++mf) {
            uint32_t addr = sb + pchunk_off(c) +
                            prow_addr(a_row0 + mf * 16, kk2 + a_us);
            ldsm4(pf[mf][0], pf[mf][1], pf[mf][2], pf[mf][3], addr);
        }
        uint32_t vf[4][2];
        const int jrow = c * 32 + (s2 & 1) * 16 + (t4 & 1) * 8 + r8;
#pragma unroll
        for (int nu = 0; nu < 2; ++nu) {
            uint32_t addr = sb + ASM_V + prow_addr(jrow, nu * 2 + (t4 >> 1));
            ldsm4t(vf[nu * 2][0], vf[nu * 2][1], vf[nu * 2 + 1][0],
                   vf[nu * 2 + 1][1], addr);
        }
#pragma unroll
        for (int mf = 0; mf < 2; ++mf)
#pragma unroll
            for (int nf = 0; nf < 4; ++nf)
                mma_f16(o[mf][nf], pf[mf], vf[nf]);
    }

    // ---- Epilogue: normalize, store fp16 att ----
    __half* ob = att + (size_t)b * Nn * Cc + h * 32;
#pragma unroll
    for (int mf = 0; mf < 2; ++mf) {
        int r0 = w * 32 + mf * 16 + qrow;
#pragma unroll
        for (int nf = 0; nf < 4; ++nf) {
            int d = nf * 8 + qc;
            uint32_t lo = pack_h2(o[mf][nf][0] * inv[mf][0], o[mf][nf][1] * inv[mf][0]);
            uint32_t hi = pack_h2(o[mf][nf][2] * inv[mf][1], o[mf][nf][3] * inv[mf][1]);
            *reinterpret_cast<uint32_t*>(ob + (size_t)r0 * Cc + d) = lo;
            *reinterpret_cast<uint32_t*>(ob + (size_t)(r0 + 8) * Cc + d) = hi;
        }
    }
}

// ---------------------------------------------------------------------------
// Launch
// ---------------------------------------------------------------------------
extern "C" void kernel_launch(void* const* d_in, const int* in_sizes, int n_in,
                              void* d_out, int out_size) {
    const float* x      = (const float*)d_in[0];
    const float* mask   = (const float*)d_in[1];
    const float* qkv_w  = (const float*)d_in[2];
    const float* qkv_b  = (const float*)d_in[3];
    const float* proj_w = (const float*)d_in[4];
    const float* proj_b = (const float*)d_in[5];
    float* out = (float*)d_out;

    __half *p_q16, *p_klo, *p_att, *p_w16, *p_pw16, *p_mask16;
    cudaGetSymbolAddress((void**)&p_q16, g_q16);
    cudaGetSymbolAddress((void**)&p_klo, g_klo);
    cudaGetSymbolAddress((void**)&p_att, g_att);
    cudaGetSymbolAddress((void**)&p_w16, g_w16);
    cudaGetSymbolAddress((void**)&p_pw16, g_pw16);
    cudaGetSymbolAddress((void**)&p_mask16, g_mask16);

    cudaFuncSetAttribute(gemm_mma<0>, cudaFuncAttributeMaxDynamicSharedMemorySize, GSM_TOTAL);
    cudaFuncSetAttribute(gemm_mma<1>, cudaFuncAttributeMaxDynamicSharedMemorySize, GSM_TOTAL);
    cudaFuncSetAttribute(attn_mma, cudaFuncAttributeMaxDynamicSharedMemorySize, ATTN_SMEM_TOT);

    // 0) fp16 prepass (weights + mask)
    prep16<<<(PREP_TOT + 255) / 256, 256>>>(mask, qkv_w, proj_w);

    // 1) QKV projection -> fp16 q(scaled)/khi/v + klo residual
    gemm_mma<0><<<dim3(3, M_TOT / 128), 256, GSM_TOTAL>>>(x, p_w16, qkv_b, nullptr);

    // 2) windowed attention per (b,h)
    attn_mma<<<Bb * Hh, 128, ATTN_SMEM_TOT>>>(p_q16, p_klo, p_mask16, p_att);

    // 3) output projection (fp16 A, fp32 out)
    gemm_mma<1><<<dim3(1, M_TOT / 128), 256, GSM_TOTAL>>>(p_att, p_pw16, proj_b, out);
}

// round 7
// speedup vs baseline: 5.6029x; 1.1299x over previous
#include <cuda_runtime.h>
#include <cuda_fp16.h>
#include <cstdint>

// Problem constants
#define Bb   2048
#define Nn   128
#define Cc   128
#define Hh   4
#define NW   64
#define M_TOT (Bb * Nn)            // 262144 rows
#define SCALE 0.1767766952966369f  // 1/sqrt(32)

// ---------------------------------------------------------------------------
// Helpers (baseline ISA: ldmatrix + mma.sync fp16)
// ---------------------------------------------------------------------------
__device__ __forceinline__ uint32_t smem_u32(const void* p) {
    uint32_t a;
    asm("{ .reg .u64 t; cvta.to.shared.u64 t, %1; cvt.u32.u64 %0, t; }"
        : "=r"(a) : "l"(p));
    return a;
}
__device__ __forceinline__ uint32_t pack_h2(float a, float b) {
    __half2 h = __floats2half2_rn(a, b);
    return *reinterpret_cast<uint32_t*>(&h);
}
__device__ __forceinline__ uint32_t pack_h2_lo(float a, float b) {
    float ah = __half2float(__float2half_rn(a));
    float bh = __half2float(__float2half_rn(b));
    return pack_h2(a - ah, b - bh);
}
__device__ __forceinline__ void ldsm4(uint32_t& r0, uint32_t& r1, uint32_t& r2,
                                      uint32_t& r3, uint32_t addr) {
    asm volatile("ldmatrix.sync.aligned.m8n8.x4.shared.b16 {%0,%1,%2,%3}, [%4];"
                 : "=r"(r0), "=r"(r1), "=r"(r2), "=r"(r3) : "r"(addr));
}
__device__ __forceinline__ void ldsm4t(uint32_t& r0, uint32_t& r1, uint32_t& r2,
                                       uint32_t& r3, uint32_t addr) {
    asm volatile("ldmatrix.sync.aligned.m8n8.x4.trans.shared.b16 {%0,%1,%2,%3}, [%4];"
                 : "=r"(r0), "=r"(r1), "=r"(r2), "=r"(r3) : "r"(addr));
}
__device__ __forceinline__ void mma_f16(float* c, const uint32_t* a,
                                        const uint32_t* b) {
    asm volatile(
        "mma.sync.aligned.m16n8k16.row.col.f32.f16.f16.f32 "
        "{%0,%1,%2,%3}, {%4,%5,%6,%7}, {%8,%9}, {%0,%1,%2,%3};"
        : "+f"(c[0]), "+f"(c[1]), "+f"(c[2]), "+f"(c[3])
        : "r"(a[0]), "r"(a[1]), "r"(a[2]), "r"(a[3]), "r"(b[0]), "r"(b[1]));
}

// ---------------------------------------------------------------------------
// Scratch
// ---------------------------------------------------------------------------
__device__ __half g_q16[(size_t)M_TOT * 3 * Cc];   // [B,N,384] fp16 (q scaled, k=hi, v)
__device__ __half g_klo[(size_t)M_TOT * Cc];       // [B,N,128] fp16 K residual
__device__ __half g_att[(size_t)M_TOT * Cc];       // [B,N,128] fp16
__device__ __half g_w16[3 * Cc * Cc];              // qkv_w fp16
__device__ __half g_pw16[Cc * Cc];                 // proj_w fp16
__device__ __half g_mask16[NW * Nn * Nn];          // mask fp16

// ---------------------------------------------------------------------------
// Prepass: weights + mask -> fp16
// ---------------------------------------------------------------------------
#define MASK2  (NW * Nn * Nn / 2)
#define QW2    (3 * Cc * Cc / 2)
#define PW2    (Cc * Cc / 2)
#define PREP_TOT (MASK2 + QW2 + PW2)

__global__ void prep16(const float* __restrict__ mask,
                       const float* __restrict__ qkv_w,
                       const float* __restrict__ proj_w) {
    int idx = blockIdx.x * blockDim.x + threadIdx.x;
    if (idx >= PREP_TOT) return;
    if (idx < MASK2) {
        float2 v = reinterpret_cast<const float2*>(mask)[idx];
        reinterpret_cast<uint32_t*>(g_mask16)[idx] = pack_h2(v.x, v.y);
    } else if (idx < MASK2 + QW2) {
        float2 v = reinterpret_cast<const float2*>(qkv_w)[idx - MASK2];
        reinterpret_cast<uint32_t*>(g_w16)[idx - MASK2] = pack_h2(v.x, v.y);
    } else {
        float2 v = reinterpret_cast<const float2*>(proj_w)[idx - MASK2 - QW2];
        reinterpret_cast<uint32_t*>(g_pw16)[idx - MASK2 - QW2] = pack_h2(v.x, v.y);
    }
}

// ---------------------------------------------------------------------------
// QKV GEMM v3: one CTA per 128-row M-tile; loops 3 weight sections through a
// single 32KB B buffer (L2-hot). A (x) loaded & converted ONCE.
// 256 threads, 8 warps (4m x 2n), warp tile 32x64. smem 64KB -> 2 CTAs/SM.
// ---------------------------------------------------------------------------
#define QSM_A     0
#define QSM_B     32768
#define QSM_TOTAL 65536

__global__ __launch_bounds__(256, 2)
void gemm_qkv(const float* __restrict__ x, const __half* __restrict__ W16,
              const float* __restrict__ bias) {
    extern __shared__ char smem[];
    const uint32_t sA = smem_u32(smem) + QSM_A;
    const uint32_t sB = smem_u32(smem) + QSM_B;
    const int tid  = threadIdx.x;
    const int wid  = tid >> 5;
    const int lane = tid & 31;
    const int mBase = blockIdx.x * 128;
    const int wm = wid & 3;      // 32 rows each
    const int wn = wid >> 2;     // 64 cols each

    // ---- A tile -> smem fp16 (once) ----
    {
        const float4* A4 = reinterpret_cast<const float4*>(x + (size_t)mBase * 128);
#pragma unroll
        for (int it = 0; it < 8; ++it) {
            int idx = it * 256 + tid;
            int m = idx >> 4, g = idx & 15;
            float4 a = A4[(size_t)m * 32 + g * 2];
            float4 b = A4[(size_t)m * 32 + g * 2 + 1];
            uint4 u = {pack_h2(a.x, a.y), pack_h2(a.z, a.w),
                       pack_h2(b.x, b.y), pack_h2(b.z, b.w)};
            *reinterpret_cast<uint4*>(
                (char*)smem + QSM_A + (g >> 3) * 16384 + m * 128 +
                16 * ((g & 7) ^ (m & 7))) = u;
        }
    }

    const int r8 = lane & 7, t = lane >> 3;
    const int a_row0 = wm * 32 + (t & 1) * 8 + r8;
    const int a_us   = t >> 1;
    const int b_roff = (t >> 1) * 8 + r8;
    const int b_us   = t & 1;
    const int qrow = lane >> 2, qc = (lane & 3) * 2;

#pragma unroll
    for (int sec = 0; sec < 3; ++sec) {
        __syncthreads();   // prior mma done (and A stores, on sec 0)
        // ---- B section -> smem (fp16 weights, L2-hot) ----
        {
            const __half* Bp = W16 + (size_t)(sec * 128) * 128;
#pragma unroll
            for (int it = 0; it < 8; ++it) {
                int idx = it * 256 + tid;
                int n = idx >> 4, g = idx & 15;
                uint4 v = reinterpret_cast<const uint4*>(Bp + (size_t)n * 128)[g];
                *reinterpret_cast<uint4*>(
                    (char*)smem + QSM_B + (g >> 3) * 16384 + n * 128 +
                    16 * ((g & 7) ^ (n & 7))) = v;
            }
        }
        __syncthreads();

        float acc[2][8][4];
#pragma unroll
        for (int i = 0; i < 2; ++i)
#pragma unroll
            for (int j = 0; j < 8; ++j)
#pragma unroll
                for (int k = 0; k < 4; ++k) acc[i][j][k] = 0.f;

        // ---- Mainloop: 8 k-steps of k=16 ----
#pragma unroll
        for (int s = 0; s < 8; ++s) {
            const int c = s >> 2;
            const int ku = (s & 3) * 2;
            uint32_t af[2][4], bf[8][2];
#pragma unroll
            for (int mf = 0; mf < 2; ++mf) {
                int row = a_row0 + mf * 16;
                uint32_t addr = sA + c * 16384 + row * 128 +
                                (((ku + a_us) * 16) ^ ((row & 7) * 16));
                ldsm4(af[mf][0], af[mf][1], af[mf][2], af[mf][3], addr);
            }
#pragma unroll
            for (int p = 0; p < 4; ++p) {
                int row = wn * 64 + p * 16 + b_roff;
                uint32_t addr = sB + c * 16384 + row * 128 +
                                (((ku + b_us) * 16) ^ ((row & 7) * 16));
                ldsm4(bf[p * 2][0], bf[p * 2][1], bf[p * 2 + 1][0],
                      bf[p * 2 + 1][1], addr);
            }
#pragma unroll
            for (int mf = 0; mf < 2; ++mf)
#pragma unroll
                for (int nf = 0; nf < 8; ++nf)
                    mma_f16(acc[mf][nf], af[mf], bf[nf]);
        }

        // ---- Epilogue: fp16 outputs (q scaled; k hi + klo residual; v) ----
#pragma unroll
        for (int mf = 0; mf < 2; ++mf) {
            const size_t r0 = (size_t)mBase + wm * 32 + mf * 16 + qrow;
#pragma unroll
            for (int nf = 0; nf < 8; ++nf) {
                const int col = sec * 128 + wn * 64 + nf * 8 + qc;
                float2 bv = *reinterpret_cast<const float2*>(&bias[col]);
                float v00 = acc[mf][nf][0] + bv.x, v01 = acc[mf][nf][1] + bv.y;
                float v10 = acc[mf][nf][2] + bv.x, v11 = acc[mf][nf][3] + bv.y;
                __half* o0 = g_q16 + r0 * 384 + col;
                __half* o1 = o0 + (size_t)8 * 384;
                if (sec == 0) {
                    *reinterpret_cast<uint32_t*>(o0) = pack_h2(v00 * SCALE, v01 * SCALE);
                    *reinterpret_cast<uint32_t*>(o1) = pack_h2(v10 * SCALE, v11 * SCALE);
                } else if (sec == 1) {
                    *reinterpret_cast<uint32_t*>(o0) = pack_h2(v00, v01);
                    *reinterpret_cast<uint32_t*>(o1) = pack_h2(v10, v11);
                    __half* l0 = g_klo + r0 * 128 + (col - 128);
                    __half* l1 = l0 + (size_t)8 * 128;
                    *reinterpret_cast<uint32_t*>(l0) = pack_h2_lo(v00, v01);
                    *reinterpret_cast<uint32_t*>(l1) = pack_h2_lo(v10, v11);
                } else {
                    *reinterpret_cast<uint32_t*>(o0) = pack_h2(v00, v01);
                    *reinterpret_cast<uint32_t*>(o1) = pack_h2(v10, v11);
                }
            }
        }
    }
}

// ---------------------------------------------------------------------------
// Proj GEMM (round-6 proven path): A fp16 (g_att), out fp32 + bias.
// ---------------------------------------------------------------------------
#define GSM_A     0
#define GSM_B     32768
#define GSM_TOTAL 65536

__global__ __launch_bounds__(256, 2)
void gemm_proj(const __half* __restrict__ A16, const __half* __restrict__ W16,
               const float* __restrict__ bias, float* __restrict__ out) {
    extern __shared__ char smem[];
    const uint32_t sA = smem_u32(smem) + GSM_A;
    const uint32_t sB = smem_u32(smem) + GSM_B;
    const int tid  = threadIdx.x;
    const int wid  = tid >> 5;
    const int lane = tid & 31;
    const int mBase = blockIdx.x * 128;
    const int wm = wid & 3;
    const int wn = wid >> 2;

    {
        const __half* Ap = A16 + (size_t)mBase * 128;
#pragma unroll
        for (int it = 0; it < 8; ++it) {
            int idx = it * 256 + tid;
            int m = idx >> 4, g = idx & 15;
            uint4 v = reinterpret_cast<const uint4*>(Ap + (size_t)m * 128)[g];
            *reinterpret_cast<uint4*>(
                (char*)smem + GSM_A + (g >> 3) * 16384 + m * 128 +
                16 * ((g & 7) ^ (m & 7))) = v;
        }
#pragma unroll
        for (int it = 0; it < 8; ++it) {
            int idx = it * 256 + tid;
            int n = idx >> 4, g = idx & 15;
            uint4 v = reinterpret_cast<const uint4*>(W16 + (size_t)n * 128)[g];
            *reinterpret_cast<uint4*>(
                (char*)smem + GSM_B + (g >> 3) * 16384 + n * 128 +
                16 * ((g & 7) ^ (n & 7))) = v;
        }
    }
    __syncthreads();

    const int r8 = lane & 7, t = lane >> 3;
    const int a_row0 = wm * 32 + (t & 1) * 8 + r8;
    const int a_us   = t >> 1;
    const int b_roff = (t >> 1) * 8 + r8;
    const int b_us   = t & 1;

    float acc[2][8][4];
#pragma unroll
    for (int i = 0; i < 2; ++i)
#pragma unroll
        for (int j = 0; j < 8; ++j)
#pragma unroll
            for (int k = 0; k < 4; ++k) acc[i][j][k] = 0.f;

#pragma unroll
    for (int s = 0; s < 8; ++s) {
        const int c = s >> 2;
        const int ku = (s & 3) * 2;
        uint32_t af[2][4], bf[8][2];
#pragma unroll
        for (int mf = 0; mf < 2; ++mf) {
            int row = a_row0 + mf * 16;
            uint32_t addr = sA + c * 16384 + row * 128 +
                            (((ku + a_us) * 16) ^ ((row & 7) * 16));
            ldsm4(af[mf][0], af[mf][1], af[mf][2], af[mf][3], addr);
        }
#pragma unroll
        for (int p = 0; p < 4; ++p) {
            int row = wn * 64 + p * 16 + b_roff;
            uint32_t addr = sB + c * 16384 + row * 128 +
                            (((ku + b_us) * 16) ^ ((row & 7) * 16));
            ldsm4(bf[p * 2][0], bf[p * 2][1], bf[p * 2 + 1][0], bf[p * 2 + 1][1],
                  addr);
        }
#pragma unroll
        for (int mf = 0; mf < 2; ++mf)
#pragma unroll
            for (int nf = 0; nf < 8; ++nf)
                mma_f16(acc[mf][nf], af[mf], bf[nf]);
    }

    const int qrow = lane >> 2, qc = (lane & 3) * 2;
#pragma unroll
    for (int mf = 0; mf < 2; ++mf) {
        const int rowg = mBase + wm * 32 + mf * 16 + qrow;
#pragma unroll
        for (int nf = 0; nf < 8; ++nf) {
            const int col = wn * 64 + nf * 8 + qc;
            float2 bv = *reinterpret_cast<const float2*>(&bias[col]);
            float2 o0 = {acc[mf][nf][0] + bv.x, acc[mf][nf][1] + bv.y};
            float2 o1 = {acc[mf][nf][2] + bv.x, acc[mf][nf][3] + bv.y};
            *reinterpret_cast<float2*>(out + (size_t)rowg * 128 + col) = o0;
            *reinterpret_cast<float2*>(out + (size_t)(rowg + 8) * 128 + col) = o1;
        }
    }
}

// ---------------------------------------------------------------------------
// Attention v3: block per (b,h), 256 threads / 8 warps, warp owns 16 q-rows.
// S acc -> PV A-fragments by register repack (FA2 style): NO P smem.
// smem: Q 8K | Khi 8K | Klo 8K | V 8K = 32KB. One __syncthreads total.
// ---------------------------------------------------------------------------
#define ASM_Q    0
#define ASM_KHI  8192
#define ASM_KLO  16384
#define ASM_V    24576
#define ATTN_SMEM_TOT 32768

__device__ __forceinline__ uint32_t prow_addr(int r, int u) {
    return (uint32_t)((r >> 1) * 128 + 16 * ((((r & 1) * 4) + u) ^ ((r >> 1) & 7)));
}

__global__ __launch_bounds__(256, 2)
void attn_mma(const __half* __restrict__ qkv16, const __half* __restrict__ klo,
              const __half* __restrict__ mask16, __half* __restrict__ att) {
    extern __shared__ char smem[];
    const uint32_t sb = smem_u32(smem);
    const int tid = threadIdx.x, lane = tid & 31, w = tid >> 5;   // w: 0..7
    const int bh = blockIdx.x, b = bh >> 2, h = bh & 3, win = b & (NW - 1);
    const __half* base  = qkv16 + (size_t)b * Nn * 384;
    const __half* lbase = klo + (size_t)b * Nn * 128;
    const __half* mbase = mask16 + (size_t)win * Nn * Nn;

    const int qrow = lane >> 2;        // 0..7
    const int qc   = (lane & 3) * 2;   // 0,2,4,6

    // ---- Load q/khi/klo/v: 256 threads, thread t -> row t>>1, half t&1 ----
    {
        const int row = tid >> 1, uh = (tid & 1) * 2;
        const uint4* qr = reinterpret_cast<const uint4*>(base + (size_t)row * 384 + h * 32);
        const uint4* kr = reinterpret_cast<const uint4*>(base + (size_t)row * 384 + 128 + h * 32);
        const uint4* vr = reinterpret_cast<const uint4*>(base + (size_t)row * 384 + 256 + h * 32);
        const uint4* lr = reinterpret_cast<const uint4*>(lbase + (size_t)row * 128 + h * 32);
#pragma unroll
        for (int du = 0; du < 2; ++du) {
            int u = uh + du;
            uint32_t so = prow_addr(row, u);
            *reinterpret_cast<uint4*>(smem + ASM_Q + so)   = qr[u];
            *reinterpret_cast<uint4*>(smem + ASM_KHI + so) = kr[u];
            *reinterpret_cast<uint4*>(smem + ASM_KLO + so) = lr[u];
            *reinterpret_cast<uint4*>(smem + ASM_V + so)   = vr[u];
        }
    }

    // ---- Accumulators initialized from fp16 mask (warp rows w*16..+16) ----
    float acc[16][4];
    {
        const __half* mr = mbase + (w * 16 + qrow) * Nn + qc;
#pragma unroll
        for (int nf = 0; nf < 16; ++nf) {
            float2 f0 = __half22float2(*reinterpret_cast<const __half2*>(mr + nf * 8));
            float2 f1 = __half22float2(*reinterpret_cast<const __half2*>(mr + 8 * Nn + nf * 8));
            acc[nf][0] = f0.x; acc[nf][1] = f0.y;
            acc[nf][2] = f1.x; acc[nf][3] = f1.y;
        }
    }
    __syncthreads();

    const int r8 = lane & 7, t4 = lane >> 3;
    const int a_us = t4 >> 1, b_us = t4 & 1;
    const int a_row0 = w * 16 + (t4 & 1) * 8 + r8;
    const int b_roff = (t4 >> 1) * 8 + r8;

    // ---- S mma: 2 k-steps (hd=32, k16), K = hi + lo ----
#pragma unroll
    for (int s = 0; s < 2; ++s) {
        const int ku = s * 2;
        uint32_t qf[4];
        ldsm4(qf[0], qf[1], qf[2], qf[3],
              sb + ASM_Q + prow_addr(a_row0, ku + a_us));
#pragma unroll
        for (int p = 0; p < 8; ++p) {
            uint32_t off = prow_addr(p * 16 + b_roff, ku + b_us);
            uint32_t kh[2][2], kl[2][2];
            ldsm4(kh[0][0], kh[0][1], kh[1][0], kh[1][1], sb + ASM_KHI + off);
            ldsm4(kl[0][0], kl[0][1], kl[1][0], kl[1][1], sb + ASM_KLO + off);
#pragma unroll
            for (int e = 0; e < 2; ++e) {
                mma_f16(acc[p * 2 + e], qf, kh[e]);
                mma_f16(acc[p * 2 + e], qf, kl[e]);
            }
        }
    }

    // ---- Register softmax (quad reductions) ----
    float inv[2];
#pragma unroll
    for (int hf = 0; hf < 2; ++hf) {
        float mx = -1e30f;
#pragma unroll
        for (int nf = 0; nf < 16; ++nf)
            mx = fmaxf(mx, fmaxf(acc[nf][hf * 2], acc[nf][hf * 2 + 1]));
        mx = fmaxf(mx, __shfl_xor_sync(0xffffffffu, mx, 1));
        mx = fmaxf(mx, __shfl_xor_sync(0xffffffffu, mx, 2));
        float sum = 0.f;
#pragma unroll
        for (int nf = 0; nf < 16; ++nf) {
            float e0 = __expf(acc[nf][hf * 2] - mx);
            float e1 = __expf(acc[nf][hf * 2 + 1] - mx);
            acc[nf][hf * 2] = e0;
            acc[nf][hf * 2 + 1] = e1;
            sum += e0 + e1;
        }
        sum += __shfl_xor_sync(0xffffffffu, sum, 1);
        sum += __shfl_xor_sync(0xffffffffu, sum, 2);
        inv[hf] = 1.f / sum;
    }

    // ---- PV mma: P comes straight from registers (FA2 repack) ----
    float o[4][4];
#pragma unroll
    for (int j = 0; j < 4; ++j)
#pragma unroll
        for (int k = 0; k < 4; ++k) o[j][k] = 0.f;

#pragma unroll
    for (int s2 = 0; s2 < 8; ++s2) {
        uint32_t pf[4] = {
            pack_h2(acc[2 * s2][0],     acc[2 * s2][1]),
            pack_h2(acc[2 * s2][2],     acc[2 * s2][3]),
            pack_h2(acc[2 * s2 + 1][0], acc[2 * s2 + 1][1]),
            pack_h2(acc[2 * s2 + 1][2], acc[2 * s2 + 1][3])};
        uint32_t vf[4][2];
        const int jrow = s2 * 16 + (t4 & 1) * 8 + r8;
#pragma unroll
        for (int nu = 0; nu < 2; ++nu) {
            uint32_t addr = sb + ASM_V + prow_addr(jrow, nu * 2 + (t4 >> 1));
            ldsm4t(vf[nu * 2][0], vf[nu * 2][1], vf[nu * 2 + 1][0],
                   vf[nu * 2 + 1][1], addr);
        }
#pragma unroll
        for (int nf = 0; nf < 4; ++nf)
            mma_f16(o[nf], pf, vf[nf]);
    }

    // ---- Epilogue: normalize, store fp16 att ----
    __half* ob = att + (size_t)b * Nn * Cc + h * 32;
    const int r0 = w * 16 + qrow;
#pragma unroll
    for (int nf = 0; nf < 4; ++nf) {
        int d = nf * 8 + qc;
        uint32_t lo = pack_h2(o[nf][0] * inv[0], o[nf][1] * inv[0]);
        uint32_t hi = pack_h2(o[nf][2] * inv[1], o[nf][3] * inv[1]);
        *reinterpret_cast<uint32_t*>(ob + (size_t)r0 * Cc + d) = lo;
        *reinterpret_cast<uint32_t*>(ob + (size_t)(r0 + 8) * Cc + d) = hi;
    }
}

// ---------------------------------------------------------------------------
// Launch
// ---------------------------------------------------------------------------
extern "C" void kernel_launch(void* const* d_in, const int* in_sizes, int n_in,
                              void* d_out, int out_size) {
    const float* x      = (const float*)d_in[0];
    const float* mask   = (const float*)d_in[1];
    const float* qkv_w  = (const float*)d_in[2];
    const float* qkv_b  = (const float*)d_in[3];
    const float* proj_w = (const float*)d_in[4];
    const float* proj_b = (const float*)d_in[5];
    float* out = (float*)d_out;

    __half *p_q16, *p_klo, *p_att, *p_w16, *p_pw16, *p_mask16;
    cudaGetSymbolAddress((void**)&p_q16, g_q16);
    cudaGetSymbolAddress((void**)&p_klo, g_klo);
    cudaGetSymbolAddress((void**)&p_att, g_att);
    cudaGetSymbolAddress((void**)&p_w16, g_w16);
    cudaGetSymbolAddress((void**)&p_pw16, g_pw16);
    cudaGetSymbolAddress((void**)&p_mask16, g_mask16);

    cudaFuncSetAttribute(gemm_qkv, cudaFuncAttributeMaxDynamicSharedMemorySize, QSM_TOTAL);
    cudaFuncSetAttribute(gemm_proj, cudaFuncAttributeMaxDynamicSharedMemorySize, GSM_TOTAL);
    cudaFuncSetAttribute(attn_mma, cudaFuncAttributeMaxDynamicSharedMemorySize, ATTN_SMEM_TOT);

    // 0) fp16 prepass (weights + mask)
    prep16<<<(PREP_TOT + 255) / 256, 256>>>(mask, qkv_w, proj_w);

    // 1) QKV projection -> fp16 q(scaled)/khi/v + klo residual (x read once)
    gemm_qkv<<<M_TOT / 128, 256, QSM_TOTAL>>>(x, p_w16, qkv_b);

    // 2) windowed attention per (b,h), register-repacked PV
    attn_mma<<<Bb * Hh, 256, ATTN_SMEM_TOT>>>(p_q16, p_klo, p_mask16, p_att);

    // 3) output projection
    gemm_proj<<<M_TOT / 128, 256, GSM_TOTAL>>>(p_att, p_pw16, proj_b, out);
}

// round 8
// speedup vs baseline: 5.8699x; 1.0476x over previous
#include <cuda_runtime.h>
#include <cuda_fp16.h>
#include <cstdint>

// Problem constants
#define Bb   2048
#define Nn   128
#define Cc   128
#define Hh   4
#define NW   64
#define M_TOT (Bb * Nn)            // 262144 rows
#define SCALE 0.1767766952966369f  // 1/sqrt(32)

// ---------------------------------------------------------------------------
// Helpers (baseline ISA: ldmatrix + mma.sync fp16 + cp.async)
// ---------------------------------------------------------------------------
__device__ __forceinline__ uint32_t smem_u32(const void* p) {
    uint32_t a;
    asm("{ .reg .u64 t; cvta.to.shared.u64 t, %1; cvt.u32.u64 %0, t; }"
        : "=r"(a) : "l"(p));
    return a;
}
__device__ __forceinline__ uint32_t pack_h2(float a, float b) {
    __half2 h = __floats2half2_rn(a, b);
    return *reinterpret_cast<uint32_t*>(&h);
}
__device__ __forceinline__ uint32_t pack_h2_lo(float a, float b) {
    float ah = __half2float(__float2half_rn(a));
    float bh = __half2float(__float2half_rn(b));
    return pack_h2(a - ah, b - bh);
}
__device__ __forceinline__ void ldsm4(uint32_t& r0, uint32_t& r1, uint32_t& r2,
                                      uint32_t& r3, uint32_t addr) {
    asm volatile("ldmatrix.sync.aligned.m8n8.x4.shared.b16 {%0,%1,%2,%3}, [%4];"
                 : "=r"(r0), "=r"(r1), "=r"(r2), "=r"(r3) : "r"(addr));
}
__device__ __forceinline__ void ldsm4t(uint32_t& r0, uint32_t& r1, uint32_t& r2,
                                       uint32_t& r3, uint32_t addr) {
    asm volatile("ldmatrix.sync.aligned.m8n8.x4.trans.shared.b16 {%0,%1,%2,%3}, [%4];"
                 : "=r"(r0), "=r"(r1), "=r"(r2), "=r"(r3) : "r"(addr));
}
__device__ __forceinline__ void mma_f16(float* c, const uint32_t* a,
                                        const uint32_t* b) {
    asm volatile(
        "mma.sync.aligned.m16n8k16.row.col.f32.f16.f16.f32 "
        "{%0,%1,%2,%3}, {%4,%5,%6,%7}, {%8,%9}, {%0,%1,%2,%3};"
        : "+f"(c[0]), "+f"(c[1]), "+f"(c[2]), "+f"(c[3])
        : "r"(a[0]), "r"(a[1]), "r"(a[2]), "r"(a[3]), "r"(b[0]), "r"(b[1]));
}
__device__ __forceinline__ void cp_async16(uint32_t saddr, const void* gaddr) {
    asm volatile("cp.async.cg.shared.global [%0], [%1], 16;"
                 :: "r"(saddr), "l"(gaddr));
}
#define CP_COMMIT() asm volatile("cp.async.commit_group;" ::: "memory")
#define CP_WAIT0()  asm volatile("cp.async.wait_group 0;" ::: "memory")

// ---------------------------------------------------------------------------
// Scratch
// ---------------------------------------------------------------------------
__device__ __half g_q16[(size_t)M_TOT * 3 * Cc];   // [B,N,384] fp16 (q scaled, k=hi, v)
__device__ __half g_klo[(size_t)M_TOT * Cc];       // [B,N,128] fp16 K residual
__device__ __half g_w16[3 * Cc * Cc];              // qkv_w fp16
__device__ __half g_pw16[Cc * Cc];                 // proj_w fp16
__device__ __half g_mask16[NW * Nn * Nn];          // mask fp16

// ---------------------------------------------------------------------------
// Prepass: weights + mask -> fp16
// ---------------------------------------------------------------------------
#define MASK2  (NW * Nn * Nn / 2)
#define QW2    (3 * Cc * Cc / 2)
#define PW2    (Cc * Cc / 2)
#define PREP_TOT (MASK2 + QW2 + PW2)

__global__ void prep16(const float* __restrict__ mask,
                       const float* __restrict__ qkv_w,
                       const float* __restrict__ proj_w) {
    int idx = blockIdx.x * blockDim.x + threadIdx.x;
    if (idx >= PREP_TOT) return;
    if (idx < MASK2) {
        float2 v = reinterpret_cast<const float2*>(mask)[idx];
        reinterpret_cast<uint32_t*>(g_mask16)[idx] = pack_h2(v.x, v.y);
    } else if (idx < MASK2 + QW2) {
        float2 v = reinterpret_cast<const float2*>(qkv_w)[idx - MASK2];
        reinterpret_cast<uint32_t*>(g_w16)[idx - MASK2] = pack_h2(v.x, v.y);
    } else {
        float2 v = reinterpret_cast<const float2*>(proj_w)[idx - MASK2 - QW2];
        reinterpret_cast<uint32_t*>(g_pw16)[idx - MASK2 - QW2] = pack_h2(v.x, v.y);
    }
}

// ---------------------------------------------------------------------------
// QKV GEMM v4: CTA per 128-row M-tile; 3 weight sections through DOUBLE-
// buffered B (cp.async overlaps next section's load with current MMAs).
// A (x) loaded & converted once. smem: A 32K | B0 32K | B1 32K = 96KB.
// ---------------------------------------------------------------------------
#define QSM_A     0
#define QSM_B0    32768
#define QSM_B1    65536
#define QSM_TOTAL 98304

__global__ __launch_bounds__(256, 2)
void gemm_qkv(const float* __restrict__ x, const __half* __restrict__ W16,
              const float* __restrict__ bias) {
    extern __shared__ char smem[];
    const uint32_t sA = smem_u32(smem) + QSM_A;
    const uint32_t sB0 = smem_u32(smem) + QSM_B0;
    const int tid  = threadIdx.x;
    const int wid  = tid >> 5;
    const int lane = tid & 31;
    const int mBase = blockIdx.x * 128;
    const int wm = wid & 3;      // 32 rows each
    const int wn = wid >> 2;     // 64 cols each

    // per-thread B-load indices (8 units of 16B per thread)
    // issue cp.async for section 0 -> B0
    {
        const __half* Bp = W16;  // sec 0
#pragma unroll
        for (int it = 0; it < 8; ++it) {
            int idx = it * 256 + tid;
            int n = idx >> 4, g = idx & 15;
            cp_async16(sB0 + (g >> 3) * 16384 + n * 128 + 16 * ((g & 7) ^ (n & 7)),
                       Bp + (size_t)n * 128 + g * 8);
        }
        CP_COMMIT();
    }

    // ---- A tile -> smem fp16 (once) ----
    {
        const float4* A4 = reinterpret_cast<const float4*>(x + (size_t)mBase * 128);
#pragma unroll
        for (int it = 0; it < 8; ++it) {
            int idx = it * 256 + tid;
            int m = idx >> 4, g = idx & 15;
            float4 a = A4[(size_t)m * 32 + g * 2];
            float4 b = A4[(size_t)m * 32 + g * 2 + 1];
            uint4 u = {pack_h2(a.x, a.y), pack_h2(a.z, a.w),
                       pack_h2(b.x, b.y), pack_h2(b.z, b.w)};
            *reinterpret_cast<uint4*>(
                (char*)smem + QSM_A + (g >> 3) * 16384 + m * 128 +
                16 * ((g & 7) ^ (m & 7))) = u;
        }
    }
    CP_WAIT0();
    __syncthreads();

    const int r8 = lane & 7, t = lane >> 3;
    const int a_row0 = wm * 32 + (t & 1) * 8 + r8;
    const int a_us   = t >> 1;
    const int b_roff = (t >> 1) * 8 + r8;
    const int b_us   = t & 1;
    const int qrow = lane >> 2, qc = (lane & 3) * 2;

#pragma unroll
    for (int sec = 0; sec < 3; ++sec) {
        // prefetch next section into the other buffer
        if (sec < 2) {
            uint32_t sBn = sB0 + ((sec + 1) & 1) * 32768;
            const __half* Bp = W16 + (size_t)((sec + 1) * 128) * 128;
#pragma unroll
            for (int it = 0; it < 8; ++it) {
                int idx = it * 256 + tid;
                int n = idx >> 4, g = idx & 15;
                cp_async16(sBn + (g >> 3) * 16384 + n * 128 + 16 * ((g & 7) ^ (n & 7)),
                           Bp + (size_t)n * 128 + g * 8);
            }
            CP_COMMIT();
        }

        const uint32_t sB = sB0 + (sec & 1) * 32768;
        float acc[2][8][4];
#pragma unroll
        for (int i = 0; i < 2; ++i)
#pragma unroll
            for (int j = 0; j < 8; ++j)
#pragma unroll
                for (int k = 0; k < 4; ++k) acc[i][j][k] = 0.f;

        // ---- Mainloop: 8 k-steps of k=16 ----
#pragma unroll
        for (int s = 0; s < 8; ++s) {
            const int c = s >> 2;
            const int ku = (s & 3) * 2;
            uint32_t af[2][4], bf[8][2];
#pragma unroll
            for (int mf = 0; mf < 2; ++mf) {
                int row = a_row0 + mf * 16;
                uint32_t addr = sA + c * 16384 + row * 128 +
                                (((ku + a_us) * 16) ^ ((row & 7) * 16));
                ldsm4(af[mf][0], af[mf][1], af[mf][2], af[mf][3], addr);
            }
#pragma unroll
            for (int p = 0; p < 4; ++p) {
                int row = wn * 64 + p * 16 + b_roff;
                uint32_t addr = sB + c * 16384 + row * 128 +
                                (((ku + b_us) * 16) ^ ((row & 7) * 16));
                ldsm4(bf[p * 2][0], bf[p * 2][1], bf[p * 2 + 1][0],
                      bf[p * 2 + 1][1], addr);
            }
#pragma unroll
            for (int mf = 0; mf < 2; ++mf)
#pragma unroll
                for (int nf = 0; nf < 8; ++nf)
                    mma_f16(acc[mf][nf], af[mf], bf[nf]);
        }

        // ---- Epilogue: fp16 outputs (q scaled; k hi + klo residual; v) ----
#pragma unroll
        for (int mf = 0; mf < 2; ++mf) {
            const size_t r0 = (size_t)mBase + wm * 32 + mf * 16 + qrow;
#pragma unroll
            for (int nf = 0; nf < 8; ++nf) {
                const int col = sec * 128 + wn * 64 + nf * 8 + qc;
                float2 bv = *reinterpret_cast<const float2*>(&bias[col]);
                float v00 = acc[mf][nf][0] + bv.x, v01 = acc[mf][nf][1] + bv.y;
                float v10 = acc[mf][nf][2] + bv.x, v11 = acc[mf][nf][3] + bv.y;
                __half* o0 = g_q16 + r0 * 384 + col;
                __half* o1 = o0 + (size_t)8 * 384;
                if (sec == 0) {
                    *reinterpret_cast<uint32_t*>(o0) = pack_h2(v00 * SCALE, v01 * SCALE);
                    *reinterpret_cast<uint32_t*>(o1) = pack_h2(v10 * SCALE, v11 * SCALE);
                } else if (sec == 1) {
                    *reinterpret_cast<uint32_t*>(o0) = pack_h2(v00, v01);
                    *reinterpret_cast<uint32_t*>(o1) = pack_h2(v10, v11);
                    __half* l0 = g_klo + r0 * 128 + (col - 128);
                    __half* l1 = l0 + (size_t)8 * 128;
                    *reinterpret_cast<uint32_t*>(l0) = pack_h2_lo(v00, v01);
                    *reinterpret_cast<uint32_t*>(l1) = pack_h2_lo(v10, v11);
                } else {
                    *reinterpret_cast<uint32_t*>(o0) = pack_h2(v00, v01);
                    *reinterpret_cast<uint32_t*>(o1) = pack_h2(v10, v11);
                }
            }
        }

        if (sec < 2) {
            CP_WAIT0();
            __syncthreads();
        }
    }
}

// ---------------------------------------------------------------------------
// Fused attention + proj: CTA per batch window b, 256 threads / 8 warps.
// Loop heads h=0..3: stream q/khi/klo/v head slices into 8KB bufs (cp.async),
// S mma (K hi/lo), register softmax, PV with register-repacked P, O -> smem
// ATT tile (swizzled GEMM-A layout). Then proj GEMM from smem: ATT @ pw + b.
// smem: PW 32K | ATT 32K | q/khi/klo/v 4x8K = 96KB -> 2 CTAs/SM.
// ---------------------------------------------------------------------------
#define FSM_PW   0
#define FSM_ATT  32768
#define FSM_Q    65536
#define FSM_KHI  73728
#define FSM_KLO  81920
#define FSM_V    90112
#define FSM_TOTAL 98304

__device__ __forceinline__ uint32_t prow_addr(int r, int u) {
    return (uint32_t)((r >> 1) * 128 + 16 * ((((r & 1) * 4) + u) ^ ((r >> 1) & 7)));
}

__global__ __launch_bounds__(256, 2)
void attn_proj(const __half* __restrict__ qkv16, const __half* __restrict__ klo,
               const __half* __restrict__ mask16, const __half* __restrict__ pw16,
               const float* __restrict__ bias_p, float* __restrict__ out) {
    extern __shared__ char smem[];
    const uint32_t sb = smem_u32(smem);
    const int tid = threadIdx.x, lane = tid & 31, w = tid >> 5;   // w: 0..7
    const int b = blockIdx.x, win = b & (NW - 1);
    const __half* base  = qkv16 + (size_t)b * Nn * 384;
    const __half* lbase = klo + (size_t)b * Nn * 128;
    const __half* mbase = mask16 + (size_t)win * Nn * Nn;

    const int qrow = lane >> 2;        // 0..7
    const int qc   = (lane & 3) * 2;   // 0,2,4,6

    // ---- Prefetch proj weights into PW (cp.async; consumed after heads) ----
    {
#pragma unroll
        for (int it = 0; it < 8; ++it) {
            int idx = it * 256 + tid;
            int n = idx >> 4, g = idx & 15;
            cp_async16(sb + FSM_PW + (g >> 3) * 16384 + n * 128 +
                           16 * ((g & 7) ^ (n & 7)),
                       pw16 + (size_t)n * 128 + g * 8);
        }
        CP_COMMIT();
    }

    const int r8 = lane & 7, t4 = lane >> 3;
    const int a_us = t4 >> 1, b_us = t4 & 1;
    const int a_row0 = w * 16 + (t4 & 1) * 8 + r8;
    const int b_roff = (t4 >> 1) * 8 + r8;

    // per-thread buf-load indices: thread t -> row t>>1, units (t&1)*2 + {0,1}
    const int lrow = tid >> 1, luh = (tid & 1) * 2;

#pragma unroll
    for (int h = 0; h < Hh; ++h) {
        if (h > 0) __syncthreads();   // prior head done reading bufs

        // ---- Stream head slices into bufs (cp.async) ----
#pragma unroll
        for (int du = 0; du < 2; ++du) {
            int u = luh + du;
            uint32_t so = prow_addr(lrow, u);
            const __half* qg = base + (size_t)lrow * 384 + h * 32 + u * 8;
            cp_async16(sb + FSM_Q + so, qg);
            cp_async16(sb + FSM_KHI + so, qg + 128);
            cp_async16(sb + FSM_V + so, qg + 256);
            cp_async16(sb + FSM_KLO + so, lbase + (size_t)lrow * 128 + h * 32 + u * 8);
        }
        CP_COMMIT();

        // ---- acc init from fp16 mask (overlaps cp.async) ----
        float acc[16][4];
        {
            const __half* mr = mbase + (w * 16 + qrow) * Nn + qc;
#pragma unroll
            for (int nf = 0; nf < 16; ++nf) {
                float2 f0 = __half22float2(*reinterpret_cast<const __half2*>(mr + nf * 8));
                float2 f1 = __half22float2(*reinterpret_cast<const __half2*>(mr + 8 * Nn + nf * 8));
                acc[nf][0] = f0.x; acc[nf][1] = f0.y;
                acc[nf][2] = f1.x; acc[nf][3] = f1.y;
            }
        }
        CP_WAIT0();
        __syncthreads();

        // ---- S mma: 2 k-steps (hd=32, k16), K = hi + lo ----
#pragma unroll
        for (int s = 0; s < 2; ++s) {
            const int ku = s * 2;
            uint32_t qf[4];
            ldsm4(qf[0], qf[1], qf[2], qf[3],
                  sb + FSM_Q + prow_addr(a_row0, ku + a_us));
#pragma unroll
            for (int p = 0; p < 8; ++p) {
                uint32_t off = prow_addr(p * 16 + b_roff, ku + b_us);
                uint32_t kh[2][2], kl[2][2];
                ldsm4(kh[0][0], kh[0][1], kh[1][0], kh[1][1], sb + FSM_KHI + off);
                ldsm4(kl[0][0], kl[0][1], kl[1][0], kl[1][1], sb + FSM_KLO + off);
#pragma unroll
                for (int e = 0; e < 2; ++e) {
                    mma_f16(acc[p * 2 + e], qf, kh[e]);
                    mma_f16(acc[p * 2 + e], qf, kl[e]);
                }
            }
        }

        // ---- Register softmax ----
        float inv[2];
#pragma unroll
        for (int hf = 0; hf < 2; ++hf) {
            float mx = -1e30f;
#pragma unroll
            for (int nf = 0; nf < 16; ++nf)
                mx = fmaxf(mx, fmaxf(acc[nf][hf * 2], acc[nf][hf * 2 + 1]));
            mx = fmaxf(mx, __shfl_xor_sync(0xffffffffu, mx, 1));
            mx = fmaxf(mx, __shfl_xor_sync(0xffffffffu, mx, 2));
            float sum = 0.f;
#pragma unroll
            for (int nf = 0; nf < 16; ++nf) {
                float e0 = __expf(acc[nf][hf * 2] - mx);
                float e1 = __expf(acc[nf][hf * 2 + 1] - mx);
                acc[nf][hf * 2] = e0;
                acc[nf][hf * 2 + 1] = e1;
                sum += e0 + e1;
            }
            sum += __shfl_xor_sync(0xffffffffu, sum, 1);
            sum += __shfl_xor_sync(0xffffffffu, sum, 2);
            inv[hf] = 1.f / sum;
        }

        // ---- PV mma: P from registers (FA2 repack) ----
        float o[4][4];
#pragma unroll
        for (int j = 0; j < 4; ++j)
#pragma unroll
            for (int k = 0; k < 4; ++k) o[j][k] = 0.f;

#pragma unroll
        for (int s2 = 0; s2 < 8; ++s2) {
            uint32_t pf[4] = {
                pack_h2(acc[2 * s2][0],     acc[2 * s2][1]),
                pack_h2(acc[2 * s2][2],     acc[2 * s2][3]),
                pack_h2(acc[2 * s2 + 1][0], acc[2 * s2 + 1][1]),
                pack_h2(acc[2 * s2 + 1][2], acc[2 * s2 + 1][3])};
            uint32_t vf[4][2];
            const int jrow = s2 * 16 + (t4 & 1) * 8 + r8;
#pragma unroll
            for (int nu = 0; nu < 2; ++nu) {
                uint32_t addr = sb + FSM_V + prow_addr(jrow, nu * 2 + (t4 >> 1));
                ldsm4t(vf[nu * 2][0], vf[nu * 2][1], vf[nu * 2 + 1][0],
                       vf[nu * 2 + 1][1], addr);
            }
#pragma unroll
            for (int nf = 0; nf < 4; ++nf)
                mma_f16(o[nf], pf, vf[nf]);
        }

        // ---- O -> ATT smem (swizzled GEMM-A layout), normalized fp16 ----
        {
            const int r0 = w * 16 + qrow;
#pragma unroll
            for (int nf = 0; nf < 4; ++nf) {
                int g = h * 4 + nf;              // 16B col unit 0..15
                uint32_t baseu = sb + FSM_ATT + (g >> 3) * 16384;
                uint32_t a0 = baseu + r0 * 128 + 16 * ((g & 7) ^ (r0 & 7)) + qc * 2;
                int r1 = r0 + 8;
                uint32_t a1 = baseu + r1 * 128 + 16 * ((g & 7) ^ (r1 & 7)) + qc * 2;
                uint32_t p0 = pack_h2(o[nf][0] * inv[0], o[nf][1] * inv[0]);
                uint32_t p1 = pack_h2(o[nf][2] * inv[1], o[nf][3] * inv[1]);
                asm volatile("st.shared.b32 [%0], %1;" :: "r"(a0), "r"(p0) : "memory");
                asm volatile("st.shared.b32 [%0], %1;" :: "r"(a1), "r"(p1) : "memory");
            }
        }
    }
    __syncthreads();   // ATT complete (and PW visible)

    // ---- Proj GEMM from smem: out[b*128..][128] = ATT @ PW^T + bias_p ----
    {
        const int wm = w & 3, wn = w >> 2;
        const int t = lane >> 3;
        const int pa_row0 = wm * 32 + (t & 1) * 8 + r8;
        const int pa_us   = t >> 1;
        const int pb_roff = (t >> 1) * 8 + r8;
        const int pb_us   = t & 1;

        float acc[2][8][4];
#pragma unroll
        for (int i = 0; i < 2; ++i)
#pragma unroll
            for (int j = 0; j < 8; ++j)
#pragma unroll
                for (int k = 0; k < 4; ++k) acc[i][j][k] = 0.f;

#pragma unroll
        for (int s = 0; s < 8; ++s) {
            const int c = s >> 2;
            const int ku = (s & 3) * 2;
            uint32_t af[2][4], bf[8][2];
#pragma unroll
            for (int mf = 0; mf < 2; ++mf) {
                int row = pa_row0 + mf * 16;
                uint32_t addr = sb + FSM_ATT + c * 16384 + row * 128 +
                                (((ku + pa_us) * 16) ^ ((row & 7) * 16));
                ldsm4(af[mf][0], af[mf][1], af[mf][2], af[mf][3], addr);
            }
#pragma unroll
            for (int p = 0; p < 4; ++p) {
                int row = wn * 64 + p * 16 + pb_roff;
                uint32_t addr = sb + FSM_PW + c * 16384 + row * 128 +
                                (((ku + pb_us) * 16) ^ ((row & 7) * 16));
                ldsm4(bf[p * 2][0], bf[p * 2][1], bf[p * 2 + 1][0],
                      bf[p * 2 + 1][1], addr);
            }
#pragma unroll
            for (int mf = 0; mf < 2; ++mf)
#pragma unroll
                for (int nf = 0; nf < 8; ++nf)
                    mma_f16(acc[mf][nf], af[mf], bf[nf]);
        }

#pragma unroll
        for (int mf = 0; mf < 2; ++mf) {
            const int rowg = b * 128 + wm * 32 + mf * 16 + qrow;
#pragma unroll
            for (int nf = 0; nf < 8; ++nf) {
                const int col = wn * 64 + nf * 8 + qc;
                float2 bv = *reinterpret_cast<const float2*>(&bias_p[col]);
                float2 o0 = {acc[mf][nf][0] + bv.x, acc[mf][nf][1] + bv.y};
                float2 o1 = {acc[mf][nf][2] + bv.x, acc[mf][nf][3] + bv.y};
                *reinterpret_cast<float2*>(out + (size_t)rowg * 128 + col) = o0;
                *reinterpret_cast<float2*>(out + (size_t)(rowg + 8) * 128 + col) = o1;
            }
        }
    }
}

// ---------------------------------------------------------------------------
// Launch
// ---------------------------------------------------------------------------
extern "C" void kernel_launch(void* const* d_in, const int* in_sizes, int n_in,
                              void* d_out, int out_size) {
    const float* x      = (const float*)d_in[0];
    const float* mask   = (const float*)d_in[1];
    const float* qkv_w  = (const float*)d_in[2];
    const float* qkv_b  = (const float*)d_in[3];
    const float* proj_w = (const float*)d_in[4];
    const float* proj_b = (const float*)d_in[5];
    float* out = (float*)d_out;

    __half *p_q16, *p_klo, *p_w16, *p_pw16, *p_mask16;
    cudaGetSymbolAddress((void**)&p_q16, g_q16);
    cudaGetSymbolAddress((void**)&p_klo, g_klo);
    cudaGetSymbolAddress((void**)&p_w16, g_w16);
    cudaGetSymbolAddress((void**)&p_pw16, g_pw16);
    cudaGetSymbolAddress((void**)&p_mask16, g_mask16);

    cudaFuncSetAttribute(gemm_qkv, cudaFuncAttributeMaxDynamicSharedMemorySize, QSM_TOTAL);
    cudaFuncSetAttribute(attn_proj, cudaFuncAttributeMaxDynamicSharedMemorySize, FSM_TOTAL);

    // 0) fp16 prepass (weights + mask)
    prep16<<<(PREP_TOT + 255) / 256, 256>>>(mask, qkv_w, proj_w);

    // 1) QKV projection -> fp16 q(scaled)/khi/v + klo (double-buffered B)
    gemm_qkv<<<M_TOT / 128, 256, QSM_TOTAL>>>(x, p_w16, qkv_b);

    // 2) fused windowed attention + output projection (CTA per window)
    attn_proj<<<Bb, 256, FSM_TOTAL>>>(p_q16, p_klo, p_mask16, p_pw16, proj_b, out);
}

// round 9
// speedup vs baseline: 8.0878x; 1.3778x over previous
#include <cuda_runtime.h>
#include <cuda_fp16.h>
#include <cstdint>

// Problem constants
#define Bb   2048
#define Nn   128
#define Cc   128
#define Hh   4
#define NW   64
#define M_TOT (Bb * Nn)            // 262144 rows
#define SCALE 0.1767766952966369f  // 1/sqrt(32)

// ---------------------------------------------------------------------------
// Helpers (baseline ISA: ldmatrix + mma.sync fp16 + cp.async)
// ---------------------------------------------------------------------------
__device__ __forceinline__ uint32_t smem_u32(const void* p) {
    uint32_t a;
    asm("{ .reg .u64 t; cvta.to.shared.u64 t, %1; cvt.u32.u64 %0, t; }"
        : "=r"(a) : "l"(p));
    return a;
}
__device__ __forceinline__ uint32_t pack_h2(float a, float b) {
    __half2 h = __floats2half2_rn(a, b);
    return *reinterpret_cast<uint32_t*>(&h);
}
__device__ __forceinline__ uint32_t pack_h2_lo(float a, float b) {
    float ah = __half2float(__float2half_rn(a));
    float bh = __half2float(__float2half_rn(b));
    return pack_h2(a - ah, b - bh);
}
__device__ __forceinline__ void ldsm4(uint32_t& r0, uint32_t& r1, uint32_t& r2,
                                      uint32_t& r3, uint32_t addr) {
    asm volatile("ldmatrix.sync.aligned.m8n8.x4.shared.b16 {%0,%1,%2,%3}, [%4];"
                 : "=r"(r0), "=r"(r1), "=r"(r2), "=r"(r3) : "r"(addr));
}
__device__ __forceinline__ void ldsm4t(uint32_t& r0, uint32_t& r1, uint32_t& r2,
                                       uint32_t& r3, uint32_t addr) {
    asm volatile("ldmatrix.sync.aligned.m8n8.x4.trans.shared.b16 {%0,%1,%2,%3}, [%4];"
                 : "=r"(r0), "=r"(r1), "=r"(r2), "=r"(r3) : "r"(addr));
}
__device__ __forceinline__ void mma_f16(float* c, const uint32_t* a,
                                        const uint32_t* b) {
    asm volatile(
        "mma.sync.aligned.m16n8k16.row.col.f32.f16.f16.f32 "
        "{%0,%1,%2,%3}, {%4,%5,%6,%7}, {%8,%9}, {%0,%1,%2,%3};"
        : "+f"(c[0]), "+f"(c[1]), "+f"(c[2]), "+f"(c[3])
        : "r"(a[0]), "r"(a[1]), "r"(a[2]), "r"(a[3]), "r"(b[0]), "r"(b[1]));
}
__device__ __forceinline__ void cp_async16(uint32_t saddr, const void* gaddr) {
    asm volatile("cp.async.cg.shared.global [%0], [%1], 16;"
                 :: "r"(saddr), "l"(gaddr));
}
#define CP_COMMIT() asm volatile("cp.async.commit_group;" ::: "memory")
#define CP_WAIT0()  asm volatile("cp.async.wait_group 0;" ::: "memory")

// ---------------------------------------------------------------------------
// Scratch (weights + mask fp16 only — no big intermediates anymore)
// ---------------------------------------------------------------------------
__device__ __half g_w16[3 * Cc * Cc];              // qkv_w fp16
__device__ __half g_pw16[Cc * Cc];                 // proj_w fp16
__device__ __half g_mask16[NW * Nn * Nn];          // mask fp16

// ---------------------------------------------------------------------------
// Prepass: weights + mask -> fp16
// ---------------------------------------------------------------------------
#define MASK2  (NW * Nn * Nn / 2)
#define QW2    (3 * Cc * Cc / 2)
#define PW2    (Cc * Cc / 2)
#define PREP_TOT (MASK2 + QW2 + PW2)

__global__ void prep16(const float* __restrict__ mask,
                       const float* __restrict__ qkv_w,
                       const float* __restrict__ proj_w) {
    int idx = blockIdx.x * blockDim.x + threadIdx.x;
    if (idx >= PREP_TOT) return;
    if (idx < MASK2) {
        float2 v = reinterpret_cast<const float2*>(mask)[idx];
        reinterpret_cast<uint32_t*>(g_mask16)[idx] = pack_h2(v.x, v.y);
    } else if (idx < MASK2 + QW2) {
        float2 v = reinterpret_cast<const float2*>(qkv_w)[idx - MASK2];
        reinterpret_cast<uint32_t*>(g_w16)[idx - MASK2] = pack_h2(v.x, v.y);
    } else {
        float2 v = reinterpret_cast<const float2*>(proj_w)[idx - MASK2 - QW2];
        reinterpret_cast<uint32_t*>(g_pw16)[idx - MASK2 - QW2] = pack_h2(v.x, v.y);
    }
}

// ---------------------------------------------------------------------------
// FULLY FUSED kernel: one CTA per batch window b. 256 threads / 8 warps.
// Phase 1 (QKV): x->XA once; W sections cp.async ping-pong (B0, VR, B0);
//   epilogues write q(scaled)/khi+klo/v straight into smem (head-chunked
//   prow layout). Phase 2 (attention): per head, S (K hi/lo) + register
//   softmax + PV (register-repacked P), O -> ATT tile (overlay B0); PW
//   prefetched into dead XA. Phase 3 (proj): smem GEMM ATT @ PW^T + bias.
// smem: XA/PW 32K | B0/ATT 32K | Q 32K | KHI 32K | KLO 32K | VR/V 32K =192KB.
// ---------------------------------------------------------------------------
#define FSM_XA   0          // x tile (QKV A)     -> later PW
#define FSM_B0   32768      // W sec0 & sec2      -> later ATT
#define FSM_Q    65536      // q, 4 head chunks x 8KB
#define FSM_KHI  98304
#define FSM_KLO  131072
#define FSM_VR   163840     // W sec1             -> later V
#define FSM_TOTAL 196608

__device__ __forceinline__ uint32_t prow_addr(int r, int u) {
    return (uint32_t)((r >> 1) * 128 + 16 * ((((r & 1) * 4) + u) ^ ((r >> 1) & 7)));
}

__global__ __launch_bounds__(256, 1)
void fused_all(const float* __restrict__ x, const __half* __restrict__ W16,
               const float* __restrict__ qkv_b, const __half* __restrict__ mask16,
               const __half* __restrict__ pw16, const float* __restrict__ bias_p,
               float* __restrict__ out) {
    extern __shared__ char smem[];
    const uint32_t sb = smem_u32(smem);
    const int tid = threadIdx.x, lane = tid & 31, w = tid >> 5;   // w: 0..7
    const int b = blockIdx.x, win = b & (NW - 1);
    const __half* mbase = mask16 + (size_t)win * Nn * Nn;

    const int qrow = lane >> 2;        // 0..7
    const int qc   = (lane & 3) * 2;   // 0,2,4,6
    const int r8 = lane & 7, t4 = lane >> 3;

    // ---- cp.async W sec0 -> B0 ----
#pragma unroll
    for (int it = 0; it < 8; ++it) {
        int idx = it * 256 + tid;
        int n = idx >> 4, g = idx & 15;
        cp_async16(sb + FSM_B0 + (g >> 3) * 16384 + n * 128 + 16 * ((g & 7) ^ (n & 7)),
                   W16 + (size_t)n * 128 + g * 8);
    }
    CP_COMMIT();

    // ---- x tile -> XA fp16 (once) ----
    {
        const float4* A4 = reinterpret_cast<const float4*>(x + (size_t)b * Nn * 128);
#pragma unroll
        for (int it = 0; it < 8; ++it) {
            int idx = it * 256 + tid;
            int m = idx >> 4, g = idx & 15;
            float4 a = A4[(size_t)m * 32 + g * 2];
            float4 c = A4[(size_t)m * 32 + g * 2 + 1];
            uint4 u = {pack_h2(a.x, a.y), pack_h2(a.z, a.w),
                       pack_h2(c.x, c.y), pack_h2(c.z, c.w)};
            *reinterpret_cast<uint4*>(
                (char*)smem + FSM_XA + (g >> 3) * 16384 + m * 128 +
                16 * ((g & 7) ^ (m & 7))) = u;
        }
    }
    CP_WAIT0();
    __syncthreads();

    // GEMM warp geometry (QKV + proj phases)
    const int wm = w & 3, wn = w >> 2;            // 4m x 2n
    const int tA = lane >> 3;
    const int ga_row0 = wm * 32 + (tA & 1) * 8 + r8;
    const int ga_us   = tA >> 1;
    const int gb_roff = (tA >> 1) * 8 + r8;
    const int gb_us   = tA & 1;

    // ================= Phase 1: QKV sections =================
#pragma unroll
    for (int sec = 0; sec < 3; ++sec) {
        // prefetch next section's W into the other buffer
        if (sec < 2) {
            const uint32_t sBn = (sec == 0) ? (sb + FSM_VR) : (sb + FSM_B0);
            const __half* Bp = W16 + (size_t)((sec + 1) * 128) * 128;
#pragma unroll
            for (int it = 0; it < 8; ++it) {
                int idx = it * 256 + tid;
                int n = idx >> 4, g = idx & 15;
                cp_async16(sBn + (g >> 3) * 16384 + n * 128 + 16 * ((g & 7) ^ (n & 7)),
                           Bp + (size_t)n * 128 + g * 8);
            }
            CP_COMMIT();
        }

        const uint32_t sB = (sec == 1) ? (sb + FSM_VR) : (sb + FSM_B0);
        float acc[2][8][4];
#pragma unroll
        for (int i = 0; i < 2; ++i)
#pragma unroll
            for (int j = 0; j < 8; ++j)
#pragma unroll
                for (int k = 0; k < 4; ++k) acc[i][j][k] = 0.f;

        // mainloop: 8 k-steps of k=16
#pragma unroll
        for (int s = 0; s < 8; ++s) {
            const int c = s >> 2;
            const int ku = (s & 3) * 2;
            uint32_t af[2][4], bf[8][2];
#pragma unroll
            for (int mf = 0; mf < 2; ++mf) {
                int row = ga_row0 + mf * 16;
                uint32_t addr = sb + FSM_XA + c * 16384 + row * 128 +
                                (((ku + ga_us) * 16) ^ ((row & 7) * 16));
                ldsm4(af[mf][0], af[mf][1], af[mf][2], af[mf][3], addr);
            }
#pragma unroll
            for (int p = 0; p < 4; ++p) {
                int row = wn * 64 + p * 16 + gb_roff;
                uint32_t addr = sB + c * 16384 + row * 128 +
                                (((ku + gb_us) * 16) ^ ((row & 7) * 16));
                ldsm4(bf[p * 2][0], bf[p * 2][1], bf[p * 2 + 1][0],
                      bf[p * 2 + 1][1], addr);
            }
#pragma unroll
            for (int mf = 0; mf < 2; ++mf)
#pragma unroll
                for (int nf = 0; nf < 8; ++nf)
                    mma_f16(acc[mf][nf], af[mf], bf[nf]);
        }

        // epilogue: + bias, pack fp16, store to head-chunked prow smem
#pragma unroll
        for (int mf = 0; mf < 2; ++mf) {
            const int r0 = wm * 32 + mf * 16 + qrow;
#pragma unroll
            for (int nf = 0; nf < 8; ++nf) {
                const int col = wn * 64 + nf * 8 + qc;           // 0..127
                float2 bv = *reinterpret_cast<const float2*>(&qkv_b[sec * 128 + col]);
                float v00 = acc[mf][nf][0] + bv.x, v01 = acc[mf][nf][1] + bv.y;
                float v10 = acc[mf][nf][2] + bv.x, v11 = acc[mf][nf][3] + bv.y;
                const uint32_t hb = (uint32_t)(wn * 2 + (nf >> 2)) * 8192;
                const uint32_t o0 = hb + prow_addr(r0, nf & 3) + qc * 2;
                const uint32_t o1 = hb + prow_addr(r0 + 8, nf & 3) + qc * 2;
                uint32_t p0, p1;
                if (sec == 0) {
                    p0 = pack_h2(v00 * SCALE, v01 * SCALE);
                    p1 = pack_h2(v10 * SCALE, v11 * SCALE);
                    asm volatile("st.shared.b32 [%0], %1;" :: "r"(sb + FSM_Q + o0), "r"(p0) : "memory");
                    asm volatile("st.shared.b32 [%0], %1;" :: "r"(sb + FSM_Q + o1), "r"(p1) : "memory");
                } else if (sec == 1) {
                    p0 = pack_h2(v00, v01);
                    p1 = pack_h2(v10, v11);
                    asm volatile("st.shared.b32 [%0], %1;" :: "r"(sb + FSM_KHI + o0), "r"(p0) : "memory");
                    asm volatile("st.shared.b32 [%0], %1;" :: "r"(sb + FSM_KHI + o1), "r"(p1) : "memory");
                    uint32_t l0 = pack_h2_lo(v00, v01);
                    uint32_t l1 = pack_h2_lo(v10, v11);
                    asm volatile("st.shared.b32 [%0], %1;" :: "r"(sb + FSM_KLO + o0), "r"(l0) : "memory");
                    asm volatile("st.shared.b32 [%0], %1;" :: "r"(sb + FSM_KLO + o1), "r"(l1) : "memory");
                } else {
                    p0 = pack_h2(v00, v01);
                    p1 = pack_h2(v10, v11);
                    asm volatile("st.shared.b32 [%0], %1;" :: "r"(sb + FSM_VR + o0), "r"(p0) : "memory");
                    asm volatile("st.shared.b32 [%0], %1;" :: "r"(sb + FSM_VR + o1), "r"(p1) : "memory");
                }
            }
        }

        if (sec < 2) CP_WAIT0();
        __syncthreads();
    }

    // ---- prefetch proj weights into (dead) XA region ----
#pragma unroll
    for (int it = 0; it < 8; ++it) {
        int idx = it * 256 + tid;
        int n = idx >> 4, g = idx & 15;
        cp_async16(sb + FSM_XA + (g >> 3) * 16384 + n * 128 + 16 * ((g & 7) ^ (n & 7)),
                   pw16 + (size_t)n * 128 + g * 8);
    }
    CP_COMMIT();

    // ================= Phase 2: attention (no syncs in head loop) ==========
    const int a_us = t4 >> 1, b_us = t4 & 1;
    const int a_row0 = w * 16 + (t4 & 1) * 8 + r8;   // warp owns 16 q-rows
    const int b_roff = (t4 >> 1) * 8 + r8;

#pragma unroll
    for (int h = 0; h < Hh; ++h) {
        const uint32_t qb  = sb + FSM_Q   + h * 8192;
        const uint32_t khb = sb + FSM_KHI + h * 8192;
        const uint32_t klb = sb + FSM_KLO + h * 8192;
        const uint32_t vb  = sb + FSM_VR  + h * 8192;

        // acc init from fp16 mask (L2-hot after head 0)
        float acc[16][4];
        {
            const __half* mr = mbase + (w * 16 + qrow) * Nn + qc;
#pragma unroll
            for (int nf = 0; nf < 16; ++nf) {
                float2 f0 = __half22float2(*reinterpret_cast<const __half2*>(mr + nf * 8));
                float2 f1 = __half22float2(*reinterpret_cast<const __half2*>(mr + 8 * Nn + nf * 8));
                acc[nf][0] = f0.x; acc[nf][1] = f0.y;
                acc[nf][2] = f1.x; acc[nf][3] = f1.y;
            }
        }

        // S mma: 2 k-steps (hd=32, k16), K = hi + lo
#pragma unroll
        for (int s = 0; s < 2; ++s) {
            const int ku = s * 2;
            uint32_t qf[4];
            ldsm4(qf[0], qf[1], qf[2], qf[3], qb + prow_addr(a_row0, ku + a_us));
#pragma unroll
            for (int p = 0; p < 8; ++p) {
                uint32_t off = prow_addr(p * 16 + b_roff, ku + b_us);
                uint32_t kh[2][2], kl[2][2];
                ldsm4(kh[0][0], kh[0][1], kh[1][0], kh[1][1], khb + off);
                ldsm4(kl[0][0], kl[0][1], kl[1][0], kl[1][1], klb + off);
#pragma unroll
                for (int e = 0; e < 2; ++e) {
                    mma_f16(acc[p * 2 + e], qf, kh[e]);
                    mma_f16(acc[p * 2 + e], qf, kl[e]);
                }
            }
        }

        // register softmax
        float inv[2];
#pragma unroll
        for (int hf = 0; hf < 2; ++hf) {
            float mx = -1e30f;
#pragma unroll
            for (int nf = 0; nf < 16; ++nf)
                mx = fmaxf(mx, fmaxf(acc[nf][hf * 2], acc[nf][hf * 2 + 1]));
            mx = fmaxf(mx, __shfl_xor_sync(0xffffffffu, mx, 1));
            mx = fmaxf(mx, __shfl_xor_sync(0xffffffffu, mx, 2));
            float sum = 0.f;
#pragma unroll
            for (int nf = 0; nf < 16; ++nf) {
                float e0 = __expf(acc[nf][hf * 2] - mx);
                float e1 = __expf(acc[nf][hf * 2 + 1] - mx);
                acc[nf][hf * 2] = e0;
                acc[nf][hf * 2 + 1] = e1;
                sum += e0 + e1;
            }
            sum += __shfl_xor_sync(0xffffffffu, sum, 1);
            sum += __shfl_xor_sync(0xffffffffu, sum, 2);
            inv[hf] = 1.f / sum;
        }

        // PV mma: P straight from registers (FA2 repack)
        float o[4][4];
#pragma unroll
        for (int j = 0; j < 4; ++j)
#pragma unroll
            for (int k = 0; k < 4; ++k) o[j][k] = 0.f;

#pragma unroll
        for (int s2 = 0; s2 < 8; ++s2) {
            uint32_t pf[4] = {
                pack_h2(acc[2 * s2][0],     acc[2 * s2][1]),
                pack_h2(acc[2 * s2][2],     acc[2 * s2][3]),
                pack_h2(acc[2 * s2 + 1][0], acc[2 * s2 + 1][1]),
                pack_h2(acc[2 * s2 + 1][2], acc[2 * s2 + 1][3])};
            uint32_t vf[4][2];
            const int jrow = s2 * 16 + (t4 & 1) * 8 + r8;
#pragma unroll
            for (int nu = 0; nu < 2; ++nu) {
                ldsm4t(vf[nu * 2][0], vf[nu * 2][1], vf[nu * 2 + 1][0],
                       vf[nu * 2 + 1][1], vb + prow_addr(jrow, nu * 2 + (t4 >> 1)));
            }
#pragma unroll
            for (int nf = 0; nf < 4; ++nf)
                mma_f16(o[nf], pf, vf[nf]);
        }

        // O -> ATT tile (overlay B0), GEMM-A swizzled layout, normalized fp16
        {
            const int r0 = w * 16 + qrow;
#pragma unroll
            for (int nf = 0; nf < 4; ++nf) {
                int g = h * 4 + nf;              // 16B col unit 0..15
                uint32_t baseu = sb + FSM_B0 + (g >> 3) * 16384;
                uint32_t a0 = baseu + r0 * 128 + 16 * ((g & 7) ^ (r0 & 7)) + qc * 2;
                int r1 = r0 + 8;
                uint32_t a1 = baseu + r1 * 128 + 16 * ((g & 7) ^ (r1 & 7)) + qc * 2;
                uint32_t p0 = pack_h2(o[nf][0] * inv[0], o[nf][1] * inv[0]);
                uint32_t p1 = pack_h2(o[nf][2] * inv[1], o[nf][3] * inv[1]);
                asm volatile("st.shared.b32 [%0], %1;" :: "r"(a0), "r"(p0) : "memory");
                asm volatile("st.shared.b32 [%0], %1;" :: "r"(a1), "r"(p1) : "memory");
            }
        }
    }

    CP_WAIT0();        // PW arrived
    __syncthreads();   // ATT complete

    // ================= Phase 3: proj GEMM from smem =================
    {
        float acc[2][8][4];
#pragma unroll
        for (int i = 0; i < 2; ++i)
#pragma unroll
            for (int j = 0; j < 8; ++j)
#pragma unroll
                for (int k = 0; k < 4; ++k) acc[i][j][k] = 0.f;

#pragma unroll
        for (int s = 0; s < 8; ++s) {
            const int c = s >> 2;
            const int ku = (s & 3) * 2;
            uint32_t af[2][4], bf[8][2];
#pragma unroll
            for (int mf = 0; mf < 2; ++mf) {
                int row = ga_row0 + mf * 16;
                uint32_t addr = sb + FSM_B0 + c * 16384 + row * 128 +
                                (((ku + ga_us) * 16) ^ ((row & 7) * 16));
                ldsm4(af[mf][0], af[mf][1], af[mf][2], af[mf][3], addr);
            }
#pragma unroll
            for (int p = 0; p < 4; ++p) {
                int row = wn * 64 + p * 16 + gb_roff;
                uint32_t addr = sb + FSM_XA + c * 16384 + row * 128 +
                                (((ku + gb_us) * 16) ^ ((row & 7) * 16));
                ldsm4(bf[p * 2][0], bf[p * 2][1], bf[p * 2 + 1][0],
                      bf[p * 2 + 1][1], addr);
            }
#pragma unroll
            for (int mf = 0; mf < 2; ++mf)
#pragma unroll
                for (int nf = 0; nf < 8; ++nf)
                    mma_f16(acc[mf][nf], af[mf], bf[nf]);
        }

#pragma unroll
        for (int mf = 0; mf < 2; ++mf) {
            const int rowg = b * 128 + wm * 32 + mf * 16 + qrow;
#pragma unroll
            for (int nf = 0; nf < 8; ++nf) {
                const int col = wn * 64 + nf * 8 + qc;
                float2 bv = *reinterpret_cast<const float2*>(&bias_p[col]);
                float2 o0 = {acc[mf][nf][0] + bv.x, acc[mf][nf][1] + bv.y};
                float2 o1 = {acc[mf][nf][2] + bv.x, acc[mf][nf][3] + bv.y};
                *reinterpret_cast<float2*>(out + (size_t)rowg * 128 + col) = o0;
                *reinterpret_cast<float2*>(out + (size_t)(rowg + 8) * 128 + col) = o1;
            }
        }
    }
}

// ---------------------------------------------------------------------------
// Launch
// ---------------------------------------------------------------------------
extern "C" void kernel_launch(void* const* d_in, const int* in_sizes, int n_in,
                              void* d_out, int out_size) {
    const float* x      = (const float*)d_in[0];
    const float* mask   = (const float*)d_in[1];
    const float* qkv_w  = (const float*)d_in[2];
    const float* qkv_b  = (const float*)d_in[3];
    const float* proj_w = (const float*)d_in[4];
    const float* proj_b = (const float*)d_in[5];
    float* out = (float*)d_out;

    __half *p_w16, *p_pw16, *p_mask16;
    cudaGetSymbolAddress((void**)&p_w16, g_w16);
    cudaGetSymbolAddress((void**)&p_pw16, g_pw16);
    cudaGetSymbolAddress((void**)&p_mask16, g_mask16);

    cudaFuncSetAttribute(fused_all, cudaFuncAttributeMaxDynamicSharedMemorySize,
                         FSM_TOTAL);

    // 0) fp16 prepass (weights + mask)
    prep16<<<(PREP_TOT + 255) / 256, 256>>>(mask, qkv_w, proj_w);

    // 1) fully fused QKV + attention + proj, one CTA per window
    fused_all<<<Bb, 256, FSM_TOTAL>>>(x, p_w16, qkv_b, p_mask16, p_pw16,
                                      proj_b, out);
}